// round 11
// baseline (speedup 1.0000x reference)
#include <cuda_runtime.h>
#include <math.h>

#define N_NODES 50000
#define N_EDGES 800000
#define NTOT    850000   // E + N self loops
#define NGRAPH  256
#define F_IN    64
#define HEADS   4
#define HC      256      // HEADS*F_IN
#define ODIM    128
#define NTHR    256
#define SMEM_BYTES 33024

// ---------------- scratch (device globals; no allocation) ----------------
__device__ float g_s   [N_NODES * HC];    // per-head weighted x sums
__device__ float g_asrc[N_NODES * HEADS];
__device__ float g_adst[N_NODES * HEADS];
__device__ float g_x2  [N_NODES * HC];    // GAT output
__device__ float g_pool[NGRAPH * HC];     // sum exp(gate)*h   (zeroed in P2 each run)
__device__ float g_gden[NGRAPH];          // sum exp(gate)     (zeroed in P2)
__device__ float g_mean[NGRAPH * HC];     // raw sum of x2     (zeroed in P2)
__device__ float g_var [NGRAPH * HC];     // raw sumsq of x2   (zeroed in P2)
__device__ float g_wsrc[HC];              // W_h^T att_src_h
__device__ float g_wdst[HC];
__device__ int   g_deg [N_NODES];         // zeroed in P2 (after scan) each run
__device__ int   g_rowptr[N_NODES + 1];
__device__ int   g_woff[N_NODES];
__device__ int2  g_csr2[NTOT];            // (edge id, src)
__device__ int   g_blk [256];
__device__ int   g_gs  [NGRAPH];
__device__ int   g_ge  [NGRAPH];
__device__ int   g_bcnt = 0;              // barrier arrive counter
__device__ int   g_bgen = 0;              // barrier generation

// ---------------- software grid barrier (grid sized for full residency) ----------------
__device__ __forceinline__ void gsync() {
    __syncthreads();
    if (threadIdx.x == 0) {
        volatile int* vgen = &g_bgen;
        int my = *vgen;
        __threadfence();
        if (atomicAdd(&g_bcnt, 1) == (int)gridDim.x - 1) {
            atomicExch(&g_bcnt, 0);
            __threadfence();
            atomicAdd(&g_bgen, 1);
        } else {
            while (*vgen == my) __nanosleep(64);
            __threadfence();
        }
    }
    __syncthreads();
}

// ---------------- the whole pipeline in one persistent kernel ----------------
__global__ void __launch_bounds__(NTHR, 4) k_all(
    const float* __restrict__ x, const int* __restrict__ ei, const int* __restrict__ batch,
    const float* __restrict__ lin_w, const float* __restrict__ att_src,
    const float* __restrict__ att_dst, const float* __restrict__ gat_bias,
    const float* __restrict__ gn_w, const float* __restrict__ gn_b,
    const float* __restrict__ gn_ms,
    const float* __restrict__ fc1_w, const float* __restrict__ fc1_b,
    const float* __restrict__ out_w, const float* __restrict__ out_b,
    const float* __restrict__ att1_w, const float* __restrict__ att1_b,
    const float* __restrict__ att2_w, const float* __restrict__ att2_b,
    float* __restrict__ out, float* __restrict__ alpha)
{
    __shared__ __align__(16) char SM[SMEM_BYTES];
    const int bid = blockIdx.x, tid = threadIdx.x;
    const int warp = tid >> 5, lane = tid & 31;
    const int NB = gridDim.x;
    const int gtid = bid * NTHR + tid;
    const int GSTR = NB * NTHR;

    // ================= P0: prew + hist + bounds =================
    if (bid == 0) {
        int h = tid >> 6, c = tid & 63;
        float as = 0.f, ad = 0.f;
        for (int j = 0; j < F_IN; j++) {
            float w = lin_w[(h * F_IN + j) * F_IN + c];
            as += att_src[h * F_IN + j] * w;
            ad += att_dst[h * F_IN + j] * w;
        }
        g_wsrc[tid] = as;
        g_wdst[tid] = ad;
    }
    for (int e = gtid; e < NTOT; e += GSTR) {
        int dst = (e < N_EDGES) ? ei[N_EDGES + e] : (e - N_EDGES);
        atomicAdd(&g_deg[dst], 1);
    }
    for (int n = gtid; n < N_NODES; n += GSTR) {
        int g = batch[n];
        if (n == 0 || batch[n - 1] != g) g_gs[g] = n;
        if (n == N_NODES - 1 || batch[n + 1] != g) g_ge[g] = n + 1;
    }
    gsync();

    // ================= P1: scores + scan1 =================
    for (int sb1 = bid; sb1 < 196; sb1 += NB) {
        int* sm = (int*)SM;
        int idx = sb1 * 256 + tid;
        int v = (idx < N_NODES) ? g_deg[idx] : 0;
        sm[tid] = v;
        __syncthreads();
#pragma unroll
        for (int o = 1; o < 256; o <<= 1) {
            int u = (tid >= o) ? sm[tid - o] : 0;
            __syncthreads();
            sm[tid] += u;
            __syncthreads();
        }
        if (idx < N_NODES) g_rowptr[idx] = sm[tid] - v;
        if (tid == 255) g_blk[sb1] = sm[255];
        __syncthreads();
    }
    for (int grp = bid; grp < 6250; grp += NB) {
        int n = grp * 8 + warp;            // always < 50000
        float2 xv = *(const float2*)&x[n * F_IN + lane * 2];
        float p0, p1, p2, p3, q0, q1, q2, q3;
        {
            float2 w;
            w = *(const float2*)&g_wsrc[0 * 64 + lane * 2]; p0 = w.x * xv.x + w.y * xv.y;
            w = *(const float2*)&g_wsrc[1 * 64 + lane * 2]; p1 = w.x * xv.x + w.y * xv.y;
            w = *(const float2*)&g_wsrc[2 * 64 + lane * 2]; p2 = w.x * xv.x + w.y * xv.y;
            w = *(const float2*)&g_wsrc[3 * 64 + lane * 2]; p3 = w.x * xv.x + w.y * xv.y;
            w = *(const float2*)&g_wdst[0 * 64 + lane * 2]; q0 = w.x * xv.x + w.y * xv.y;
            w = *(const float2*)&g_wdst[1 * 64 + lane * 2]; q1 = w.x * xv.x + w.y * xv.y;
            w = *(const float2*)&g_wdst[2 * 64 + lane * 2]; q2 = w.x * xv.x + w.y * xv.y;
            w = *(const float2*)&g_wdst[3 * 64 + lane * 2]; q3 = w.x * xv.x + w.y * xv.y;
        }
#pragma unroll
        for (int o = 16; o; o >>= 1) {
            p0 += __shfl_xor_sync(0xFFFFFFFFu, p0, o);
            p1 += __shfl_xor_sync(0xFFFFFFFFu, p1, o);
            p2 += __shfl_xor_sync(0xFFFFFFFFu, p2, o);
            p3 += __shfl_xor_sync(0xFFFFFFFFu, p3, o);
            q0 += __shfl_xor_sync(0xFFFFFFFFu, q0, o);
            q1 += __shfl_xor_sync(0xFFFFFFFFu, q1, o);
            q2 += __shfl_xor_sync(0xFFFFFFFFu, q2, o);
            q3 += __shfl_xor_sync(0xFFFFFFFFu, q3, o);
        }
        if (lane == 0) {
            float4 a = {p0, p1, p2, p3};
            float4 bb = {q0, q1, q2, q3};
            *(float4*)&g_asrc[n * HEADS] = a;
            *(float4*)&g_adst[n * HEADS] = bb;
        }
    }
    gsync();

    // ================= P2: scan23 + self-clean zeroing =================
    for (int sb2 = bid; sb2 < 196; sb2 += NB) {
        int* sm = (int*)SM;
        sm[tid] = (tid < sb2) ? g_blk[tid] : 0;
        __syncthreads();
#pragma unroll
        for (int o = 128; o; o >>= 1) {
            if (tid < o) sm[tid] += sm[tid + o];
            __syncthreads();
        }
        int off = sm[0];
        int idx = sb2 * 256 + tid;
        if (idx < N_NODES) {
            int r = g_rowptr[idx] + off;
            g_rowptr[idx] = r;
            g_woff[idx] = r;
        }
        if (sb2 == 0 && tid == 0) g_rowptr[N_NODES] = NTOT;
        __syncthreads();
    }
    for (int i = gtid; i < N_NODES; i += GSTR) g_deg[i] = 0;
    for (int i = gtid; i < NGRAPH * HC; i += GSTR) { g_mean[i] = 0.f; g_var[i] = 0.f; g_pool[i] = 0.f; }
    for (int i = gtid; i < NGRAPH; i += GSTR) g_gden[i] = 0.f;
    gsync();

    // ================= P3: fill CSR =================
    for (int e = gtid; e < NTOT; e += GSTR) {
        int src, dst;
        if (e < N_EDGES) { src = ei[e]; dst = ei[N_EDGES + e]; }
        else             { src = dst = e - N_EDGES; }
        int pos = atomicAdd(&g_woff[dst], 1);
        int2 es; es.x = e; es.y = src;
        g_csr2[pos] = es;
    }
    gsync();

    // ================= P4: GAT softmax + raw-x aggregation =================
    for (int grp = bid; grp < 6250; grp += NB) {
        int n = grp * 8 + warp;
        int start = g_rowptr[n], end = g_rowptr[n + 1];
        int d = end - start;
        float4 ad = *(const float4*)&g_adst[n * HEADS];
        int c0 = lane * 2;
        float2 a0 = {0.f,0.f}, a1 = {0.f,0.f}, a2 = {0.f,0.f}, a3 = {0.f,0.f};

        if (d <= 32) {
            int e = 0, src = 0;
            float4 rv = {-INFINITY, -INFINITY, -INFINITY, -INFINITY};
            if (lane < d) {
                int2 es = g_csr2[start + lane];
                e = es.x; src = es.y;
                float4 as = *(const float4*)&g_asrc[src * HEADS];
                float v;
                v = as.x + ad.x; rv.x = (v > 0.f) ? v : 0.2f * v;
                v = as.y + ad.y; rv.y = (v > 0.f) ? v : 0.2f * v;
                v = as.z + ad.z; rv.z = (v > 0.f) ? v : 0.2f * v;
                v = as.w + ad.w; rv.w = (v > 0.f) ? v : 0.2f * v;
            }
            float m0 = rv.x, m1 = rv.y, m2 = rv.z, m3 = rv.w;
#pragma unroll
            for (int o = 16; o; o >>= 1) {
                m0 = fmaxf(m0, __shfl_xor_sync(0xFFFFFFFFu, m0, o));
                m1 = fmaxf(m1, __shfl_xor_sync(0xFFFFFFFFu, m1, o));
                m2 = fmaxf(m2, __shfl_xor_sync(0xFFFFFFFFu, m2, o));
                m3 = fmaxf(m3, __shfl_xor_sync(0xFFFFFFFFu, m3, o));
            }
            float4 av = {0.f, 0.f, 0.f, 0.f};
            if (lane < d) {
                av.x = __expf(rv.x - m0);
                av.y = __expf(rv.y - m1);
                av.z = __expf(rv.z - m2);
                av.w = __expf(rv.w - m3);
            }
            float s0 = av.x, s1 = av.y, s2 = av.z, s3 = av.w;
#pragma unroll
            for (int o = 16; o; o >>= 1) {
                s0 += __shfl_xor_sync(0xFFFFFFFFu, s0, o);
                s1 += __shfl_xor_sync(0xFFFFFFFFu, s1, o);
                s2 += __shfl_xor_sync(0xFFFFFFFFu, s2, o);
                s3 += __shfl_xor_sync(0xFFFFFFFFu, s3, o);
            }
            av.x *= 1.f / (s0 + 1e-16f);
            av.y *= 1.f / (s1 + 1e-16f);
            av.z *= 1.f / (s2 + 1e-16f);
            av.w *= 1.f / (s3 + 1e-16f);
            if (lane < d) *(float4*)&alpha[e * 4] = av;
#pragma unroll 8
            for (int li = 0; li < d; li++) {
                int sb  = __shfl_sync(0xFFFFFFFFu, src, li);
                float w0 = __shfl_sync(0xFFFFFFFFu, av.x, li);
                float w1 = __shfl_sync(0xFFFFFFFFu, av.y, li);
                float w2 = __shfl_sync(0xFFFFFFFFu, av.z, li);
                float w3 = __shfl_sync(0xFFFFFFFFu, av.w, li);
                float2 xv = *(const float2*)&x[sb * F_IN + c0];
                a0.x += w0 * xv.x; a0.y += w0 * xv.y;
                a1.x += w1 * xv.x; a1.y += w1 * xv.y;
                a2.x += w2 * xv.x; a2.y += w2 * xv.y;
                a3.x += w3 * xv.x; a3.y += w3 * xv.y;
            }
        } else {
            // slow path (rare): chunked, register-only, 3 passes
            float m0 = -INFINITY, m1 = -INFINITY, m2 = -INFINITY, m3 = -INFINITY;
            for (int i = start + lane; i < end; i += 32) {
                int2 es = g_csr2[i];
                float4 as = *(const float4*)&g_asrc[es.y * HEADS];
                float v, r;
                v = as.x + ad.x; r = (v > 0.f) ? v : 0.2f * v; m0 = fmaxf(m0, r);
                v = as.y + ad.y; r = (v > 0.f) ? v : 0.2f * v; m1 = fmaxf(m1, r);
                v = as.z + ad.z; r = (v > 0.f) ? v : 0.2f * v; m2 = fmaxf(m2, r);
                v = as.w + ad.w; r = (v > 0.f) ? v : 0.2f * v; m3 = fmaxf(m3, r);
            }
#pragma unroll
            for (int o = 16; o; o >>= 1) {
                m0 = fmaxf(m0, __shfl_xor_sync(0xFFFFFFFFu, m0, o));
                m1 = fmaxf(m1, __shfl_xor_sync(0xFFFFFFFFu, m1, o));
                m2 = fmaxf(m2, __shfl_xor_sync(0xFFFFFFFFu, m2, o));
                m3 = fmaxf(m3, __shfl_xor_sync(0xFFFFFFFFu, m3, o));
            }
            float s0 = 0.f, s1 = 0.f, s2 = 0.f, s3 = 0.f;
            for (int i = start + lane; i < end; i += 32) {
                int2 es = g_csr2[i];
                float4 as = *(const float4*)&g_asrc[es.y * HEADS];
                float v, r; float4 ev;
                v = as.x + ad.x; r = (v > 0.f) ? v : 0.2f * v; ev.x = __expf(r - m0); s0 += ev.x;
                v = as.y + ad.y; r = (v > 0.f) ? v : 0.2f * v; ev.y = __expf(r - m1); s1 += ev.y;
                v = as.z + ad.z; r = (v > 0.f) ? v : 0.2f * v; ev.z = __expf(r - m2); s2 += ev.z;
                v = as.w + ad.w; r = (v > 0.f) ? v : 0.2f * v; ev.w = __expf(r - m3); s3 += ev.w;
                *(float4*)&alpha[es.x * 4] = ev;
            }
#pragma unroll
            for (int o = 16; o; o >>= 1) {
                s0 += __shfl_xor_sync(0xFFFFFFFFu, s0, o);
                s1 += __shfl_xor_sync(0xFFFFFFFFu, s1, o);
                s2 += __shfl_xor_sync(0xFFFFFFFFu, s2, o);
                s3 += __shfl_xor_sync(0xFFFFFFFFu, s3, o);
            }
            float i0 = 1.f / (s0 + 1e-16f), i1 = 1.f / (s1 + 1e-16f);
            float i2 = 1.f / (s2 + 1e-16f), i3 = 1.f / (s3 + 1e-16f);
            for (int base = start; base < end; base += 32) {
                int li = base + lane;
                int cl = min(32, end - base);
                int src = 0; float4 av = {0.f, 0.f, 0.f, 0.f};
                if (li < end) {
                    int2 es = g_csr2[li];
                    src = es.y;
                    av = *(float4*)&alpha[es.x * 4];
                    av.x *= i0; av.y *= i1; av.z *= i2; av.w *= i3;
                    *(float4*)&alpha[es.x * 4] = av;
                }
                for (int k = 0; k < cl; k++) {
                    int sb  = __shfl_sync(0xFFFFFFFFu, src, k);
                    float w0 = __shfl_sync(0xFFFFFFFFu, av.x, k);
                    float w1 = __shfl_sync(0xFFFFFFFFu, av.y, k);
                    float w2 = __shfl_sync(0xFFFFFFFFu, av.z, k);
                    float w3 = __shfl_sync(0xFFFFFFFFu, av.w, k);
                    float2 xv = *(const float2*)&x[sb * F_IN + c0];
                    a0.x += w0 * xv.x; a0.y += w0 * xv.y;
                    a1.x += w1 * xv.x; a1.y += w1 * xv.y;
                    a2.x += w2 * xv.x; a2.y += w2 * xv.y;
                    a3.x += w3 * xv.x; a3.y += w3 * xv.y;
                }
            }
        }
        *(float2*)&g_s[n * HC + 0 * 64 + c0] = a0;
        *(float2*)&g_s[n * HC + 1 * 64 + c0] = a1;
        *(float2*)&g_s[n * HC + 2 * 64 + c0] = a2;
        *(float2*)&g_s[n * HC + 3 * 64 + c0] = a3;
    }
    gsync();

    // ================= P5: W-GEMV (L1 weights) + GraphNorm stats =================
    {
        float* ss = (float*)SM;                 // 8 nodes x 256 ch = 8KB
        int*   sb = (int*)(SM + 8 * HC * 4);
        int j = tid;
        int hoff = (j >> 6) * 64;
        const float4* W4 = (const float4*)lin_w + j * 16;
        float bj = gat_bias[j];
        for (int grp = bid; grp < 6250; grp += NB) {
            int n0 = grp * 8;
            __syncthreads();
            for (int t = tid; t < 8 * HC; t += NTHR) ss[t] = g_s[n0 * HC + t];
            if (tid < 8) sb[tid] = batch[n0 + tid];
            __syncthreads();
            float sum = 0.f, sq = 0.f;
            int curg = sb[0];
#pragma unroll
            for (int nn = 0; nn < 8; nn++) {
                int g = sb[nn];
                if (g != curg) {
                    atomicAdd(&g_mean[curg * HC + j], sum);
                    atomicAdd(&g_var[curg * HC + j], sq);
                    sum = 0.f; sq = 0.f; curg = g;
                }
                const float4* sp = (const float4*)&ss[nn * HC + hoff];
                float acc = 0.f;
#pragma unroll
                for (int c4 = 0; c4 < 16; c4++) {
                    float4 w = W4[c4];
                    float4 v = sp[c4];
                    acc += v.x * w.x + v.y * w.y + v.z * w.z + v.w * w.w;
                }
                acc += bj;
                g_x2[(n0 + nn) * HC + j] = acc;
                sum += acc; sq += acc * acc;
            }
            atomicAdd(&g_mean[curg * HC + j], sum);
            atomicAdd(&g_var[curg * HC + j], sq);
        }
    }
    gsync();

    // ================= P6: norm-apply + ReLU + gate MLP + pool =================
    {
        float* wsT = (float*)SM;                         // 16KB [c][k]
        float* hs  = (float*)(SM + 16384);               // 16KB
        float* eg  = (float*)(SM + 32768);               // 64B
        int*   sb  = (int*)(SM + 32768 + 64);            // 64B
        for (int t = tid; t < 16 * HC; t += NTHR) {
            int k = t >> 8, c = t & 255;
            wsT[c * 16 + k] = att1_w[t];
        }
        float msj = gn_ms[tid], wj = gn_w[tid], bj = gn_b[tid];
        for (int grp = bid; grp < 3125; grp += NB) {
            int n0 = grp * 16;
            __syncthreads();
            if (tid < 16) sb[tid] = batch[n0 + tid];
            __syncthreads();
            int lastg = -1;
            float cA = 0.f, cB = 0.f;
#pragma unroll 4
            for (int nn = 0; nn < 16; nn++) {
                int g = sb[nn];
                if (g != lastg) {
                    float cnt = fmaxf((float)(g_ge[g] - g_gs[g]), 1.f);
                    float inv = 1.f / cnt;
                    float mean = g_mean[g * HC + tid] * inv;
                    float ex2 = g_var[g * HC + tid] * inv;
                    float mm = mean * msj;
                    float var = ex2 - 2.f * mm * mean + mm * mm;
                    cA = wj * rsqrtf(var + 1e-5f);
                    cB = bj - cA * mm;
                    lastg = g;
                }
                hs[nn * HC + tid] = fmaxf(cA * g_x2[(n0 + nn) * HC + tid] + cB, 0.f);
            }
            __syncthreads();
            {
                int nn = tid >> 4, k = tid & 15;
                float acc = att1_b[k];
                const float4* hp = (const float4*)&hs[nn * HC];
#pragma unroll 8
                for (int c4 = 0; c4 < HC / 4; c4++) {
                    float4 v = hp[c4];
                    int c = c4 * 4;
                    acc += v.x * wsT[c * 16 + k] + v.y * wsT[(c + 1) * 16 + k]
                         + v.z * wsT[(c + 2) * 16 + k] + v.w * wsT[(c + 3) * 16 + k];
                }
                float r = fmaxf(acc, 0.f) * att2_w[k];
#pragma unroll
                for (int o = 8; o; o >>= 1) r += __shfl_xor_sync(0xFFFFFFFFu, r, o);
                if (k == 0) {
                    float gate = 1.f / (1.f + __expf(-(r + att2_b[0])));
                    eg[nn] = __expf(gate);
                }
            }
            __syncthreads();
            float pacc = 0.f;
            int curg = sb[0];
#pragma unroll 4
            for (int nn = 0; nn < 16; nn++) {
                int g = sb[nn];
                if (g != curg) {
                    atomicAdd(&g_pool[curg * HC + tid], pacc);
                    pacc = 0.f; curg = g;
                }
                pacc += eg[nn] * hs[nn * HC + tid];
            }
            atomicAdd(&g_pool[curg * HC + tid], pacc);
            if (tid < 16) atomicAdd(&g_gden[sb[tid]], eg[tid]);
        }
    }
    gsync();

    // ================= P7: head =================
    for (int g = bid; g < NGRAPH; g += NB) {
        float* red = (float*)SM;
        float acc = 0.f;
        if (tid < ODIM) {
            float invZ = 1.f / (g_gden[g] + 1e-16f);
            acc = fc1_b[tid];
            const float* p = &g_pool[g * HC];
            const float* w = &fc1_w[tid * HC];
#pragma unroll 8
            for (int c = 0; c < HC; c++) acc += p[c] * invZ * w[c];
            acc = fmaxf(acc, 0.f) * out_w[tid];
        }
        __syncthreads();
        red[tid] = (tid < ODIM) ? acc : 0.f;
        __syncthreads();
#pragma unroll
        for (int s = 128; s; s >>= 1) {
            if (tid < s) red[tid] += red[tid + s];
            __syncthreads();
        }
        if (tid == 0) out[g] = 1.f / (1.f + __expf(-(red[0] + out_b[0])));
        __syncthreads();
    }
}

// ---------------- launch ----------------
extern "C" void kernel_launch(void* const* d_in, const int* in_sizes, int n_in,
                              void* d_out, int out_size) {
    const float* x        = (const float*)d_in[0];
    const int*   ei       = (const int*)  d_in[1];
    const int*   batch    = (const int*)  d_in[2];
    const float* lin_w    = (const float*)d_in[3];
    const float* att_src  = (const float*)d_in[4];
    const float* att_dst  = (const float*)d_in[5];
    const float* gat_bias = (const float*)d_in[6];
    const float* gn_w     = (const float*)d_in[7];
    const float* gn_b     = (const float*)d_in[8];
    const float* gn_ms    = (const float*)d_in[9];
    const float* fc1_w    = (const float*)d_in[10];
    const float* fc1_b    = (const float*)d_in[11];
    const float* out_w    = (const float*)d_in[12];
    const float* out_b    = (const float*)d_in[13];
    const float* att1_w   = (const float*)d_in[14];
    const float* att1_b   = (const float*)d_in[15];
    const float* att2_w   = (const float*)d_in[16];
    const float* att2_b   = (const float*)d_in[17];

    float* out   = (float*)d_out;
    float* alpha = out + NGRAPH;   // [NTOT, HEADS]

    // Size the grid for guaranteed full residency (deadlock-proof barrier).
    int dev = 0, sms = 0, bpm = 0;
    cudaGetDevice(&dev);
    cudaDeviceGetAttribute(&sms, cudaDevAttrMultiProcessorCount, dev);
    cudaOccupancyMaxActiveBlocksPerMultiprocessor(&bpm, (const void*)k_all, NTHR, 0);
    if (bpm < 1) bpm = 1;
    if (bpm > 4) bpm = 4;
    int nb = sms * bpm;
    if (nb > 592) nb = 592;
    if (nb < 1) nb = 148;

    k_all<<<nb, NTHR>>>(x, ei, batch, lin_w, att_src, att_dst, gat_bias,
                        gn_w, gn_b, gn_ms, fc1_w, fc1_b, out_w, out_b,
                        att1_w, att1_b, att2_w, att2_b, out, alpha);
}

// round 12
// speedup vs baseline: 1.6469x; 1.6469x over previous
#include <cuda_runtime.h>
#include <math.h>

#define N_NODES 50000
#define N_EDGES 800000
#define NTOT    850000   // E + N self loops
#define NGRAPH  256
#define F_IN    64
#define HEADS   4
#define HC      256      // HEADS*F_IN
#define ODIM    128
#define NBLK_SCAN 196    // ceil(N_NODES/256)

// ---------------- scratch (device globals; no allocation) ----------------
__device__ float g_s   [N_NODES * HC];    // per-head weighted x sums
__device__ float g_asrc[N_NODES * HEADS];
__device__ float g_adst[N_NODES * HEADS];
__device__ float g_x2  [N_NODES * HC];    // GAT output
__device__ float g_pool[NGRAPH * HC];     // sum exp(gate)*h
__device__ float g_gden[NGRAPH];          // sum exp(gate)
__device__ float g_mean[NGRAPH * HC];     // raw sum of x2
__device__ float g_var [NGRAPH * HC];     // raw sumsq of x2
__device__ float g_wsrc[HC];              // W_h^T att_src_h
__device__ float g_wdst[HC];
__device__ int   g_deg [N_NODES];
__device__ int   g_rowptr[N_NODES + 1];
__device__ int   g_woff[N_NODES];
__device__ int2  g_csr2[NTOT];            // (edge id, src)
__device__ int   g_blk [256];
__device__ int   g_gs  [NGRAPH];
__device__ int   g_ge  [NGRAPH];

// ---------------- front: init + prew + scores + hist + bounds in one grid ----------------
// block layout: [0, IN_BLKS) init; [IN_BLKS] prew; then scores / hist / bounds
#define IN_BLKS 257
#define SC_BLKS 6250
#define HI_BLKS 3321
#define BD_BLKS 196
#define FR_BLKS (IN_BLKS + 1 + SC_BLKS + HI_BLKS + BD_BLKS)
__global__ __launch_bounds__(256) void k_front(const float* __restrict__ x,
                                               const int* __restrict__ ei,
                                               const int* __restrict__ batch,
                                               const float* __restrict__ lin_w,
                                               const float* __restrict__ att_src,
                                               const float* __restrict__ att_dst) {
    int b = blockIdx.x;
    if (b < IN_BLKS) {
        int i = b * 256 + threadIdx.x;
        if (i < N_NODES) g_deg[i] = 0;
        if (i < NGRAPH * HC) { g_mean[i] = 0.f; g_var[i] = 0.f; g_pool[i] = 0.f; }
        if (i < NGRAPH) { g_gden[i] = 0.f; }
        return;
    }
    if (b == IN_BLKS) {
        int t = threadIdx.x;          // t = h*64 + c
        int h = t >> 6, c = t & 63;
        float as = 0.f, ad = 0.f;
        for (int j = 0; j < F_IN; j++) {
            float w = lin_w[(h * F_IN + j) * F_IN + c];
            as += att_src[h * F_IN + j] * w;
            ad += att_dst[h * F_IN + j] * w;
        }
        g_wsrc[t] = as;
        g_wdst[t] = ad;
        return;
    }
    b -= IN_BLKS + 1;
    if (b < SC_BLKS) {
        // NOTE: scores need g_wsrc/g_wdst from the prew block. These run in the
        // same launch, so we recompute the dot locally instead of reading g_wsrc.
        // (grid-order is not guaranteed) -> compute from lin_w directly via the
        // same reduction shape: each warp handles one node.
        int warp = threadIdx.x >> 5, lane = threadIdx.x & 31;
        int n = b * 8 + warp;
        if (n >= N_NODES) return;
        // load x row fragment
        float2 xv = *(const float2*)&x[n * F_IN + lane * 2];
        // compute w~ fragments on the fly: w~[h][c] = sum_j att[h][j]*W[h*64+j][c]
        // That is 64 mults per (h,c) — too heavy per node. Instead each warp
        // computes scores via shared per-block cache of w~ built once per block.
        __shared__ float ws[HC], wd[HC];
        if (threadIdx.x < HC) {
            int t = threadIdx.x;
            int h = t >> 6, c = t & 63;
            float as = 0.f, ad = 0.f;
            for (int j = 0; j < F_IN; j++) {
                float w = lin_w[(h * F_IN + j) * F_IN + c];
                as += att_src[h * F_IN + j] * w;
                ad += att_dst[h * F_IN + j] * w;
            }
            ws[t] = as; wd[t] = ad;
        }
        __syncthreads();
        float p0, p1, p2, p3, q0, q1, q2, q3;
        {
            float2 w;
            w = *(const float2*)&ws[0 * 64 + lane * 2]; p0 = w.x * xv.x + w.y * xv.y;
            w = *(const float2*)&ws[1 * 64 + lane * 2]; p1 = w.x * xv.x + w.y * xv.y;
            w = *(const float2*)&ws[2 * 64 + lane * 2]; p2 = w.x * xv.x + w.y * xv.y;
            w = *(const float2*)&ws[3 * 64 + lane * 2]; p3 = w.x * xv.x + w.y * xv.y;
            w = *(const float2*)&wd[0 * 64 + lane * 2]; q0 = w.x * xv.x + w.y * xv.y;
            w = *(const float2*)&wd[1 * 64 + lane * 2]; q1 = w.x * xv.x + w.y * xv.y;
            w = *(const float2*)&wd[2 * 64 + lane * 2]; q2 = w.x * xv.x + w.y * xv.y;
            w = *(const float2*)&wd[3 * 64 + lane * 2]; q3 = w.x * xv.x + w.y * xv.y;
        }
#pragma unroll
        for (int o = 16; o; o >>= 1) {
            p0 += __shfl_xor_sync(0xFFFFFFFFu, p0, o);
            p1 += __shfl_xor_sync(0xFFFFFFFFu, p1, o);
            p2 += __shfl_xor_sync(0xFFFFFFFFu, p2, o);
            p3 += __shfl_xor_sync(0xFFFFFFFFu, p3, o);
            q0 += __shfl_xor_sync(0xFFFFFFFFu, q0, o);
            q1 += __shfl_xor_sync(0xFFFFFFFFu, q1, o);
            q2 += __shfl_xor_sync(0xFFFFFFFFu, q2, o);
            q3 += __shfl_xor_sync(0xFFFFFFFFu, q3, o);
        }
        if (lane == 0) {
            float4 a = {p0, p1, p2, p3};
            float4 bb = {q0, q1, q2, q3};
            *(float4*)&g_asrc[n * HEADS] = a;
            *(float4*)&g_adst[n * HEADS] = bb;
        }
    } else if (b < SC_BLKS + HI_BLKS) {
        int e = (b - SC_BLKS) * 256 + threadIdx.x;
        if (e >= NTOT) return;
        int dst = (e < N_EDGES) ? ei[N_EDGES + e] : (e - N_EDGES);
        atomicAdd(&g_deg[dst], 1);
    } else {
        int n = (b - SC_BLKS - HI_BLKS) * 256 + threadIdx.x;
        if (n >= N_NODES) return;
        int g = batch[n];
        if (n == 0 || batch[n - 1] != g) g_gs[g] = n;
        if (n == N_NODES - 1 || batch[n + 1] != g) g_ge[g] = n + 1;
    }
}

// ---------------- CSR scan (2 kernels) ----------------
__global__ void k_scan1() {
    __shared__ int sm[256];
    int b = blockIdx.x, t = threadIdx.x;
    int idx = b * 256 + t;
    int v = (idx < N_NODES) ? g_deg[idx] : 0;
    sm[t] = v;
    __syncthreads();
#pragma unroll
    for (int o = 1; o < 256; o <<= 1) {
        int u = (t >= o) ? sm[t - o] : 0;
        __syncthreads();
        sm[t] += u;
        __syncthreads();
    }
    if (idx < N_NODES) g_rowptr[idx] = sm[t] - v;
    if (t == 255) g_blk[b] = sm[255];
}

__global__ void k_scan23() {
    __shared__ int sm[256];
    int b = blockIdx.x, t = threadIdx.x;
    sm[t] = (t < b) ? g_blk[t] : 0;   // sum of preceding block aggregates
    __syncthreads();
#pragma unroll
    for (int o = 128; o; o >>= 1) {
        if (t < o) sm[t] += sm[t + o];
        __syncthreads();
    }
    int off = sm[0];
    int idx = b * 256 + t;
    if (idx < N_NODES) {
        int r = g_rowptr[idx] + off;
        g_rowptr[idx] = r;
        g_woff[idx] = r;
    }
    if (b == 0 && t == 0) g_rowptr[N_NODES] = NTOT;
}

__global__ void k_fill(const int* __restrict__ ei) {
    int e = blockIdx.x * blockDim.x + threadIdx.x;
    if (e >= NTOT) return;
    int src, dst;
    if (e < N_EDGES) { src = ei[e]; dst = ei[N_EDGES + e]; }
    else             { src = dst = e - N_EDGES; }
    int pos = atomicAdd(&g_woff[dst], 1);
    int2 es; es.x = e; es.y = src;
    g_csr2[pos] = es;
}

// ---------------- fused GAT: warp per dst node, register-resident ----------------
#define GAT_WARPS 8
__global__ __launch_bounds__(256, 6) void k_gat(const float* __restrict__ x,
                                                float* __restrict__ alpha) {
    int warp = threadIdx.x >> 5;
    int lane = threadIdx.x & 31;
    int n = blockIdx.x * GAT_WARPS + warp;
    if (n >= N_NODES) return;
    int start = g_rowptr[n], end = g_rowptr[n + 1];
    int d = end - start;
    float4 ad = *(const float4*)&g_adst[n * HEADS];
    int c0 = lane * 2;

    float2 a0 = {0.f,0.f}, a1 = {0.f,0.f}, a2 = {0.f,0.f}, a3 = {0.f,0.f};

    if (d <= 32) {
        int e = 0, src = 0;
        float4 rv = {-INFINITY, -INFINITY, -INFINITY, -INFINITY};
        if (lane < d) {
            int2 es = g_csr2[start + lane];
            e = es.x; src = es.y;
            float4 as = *(const float4*)&g_asrc[src * HEADS];
            float v;
            v = as.x + ad.x; rv.x = (v > 0.f) ? v : 0.2f * v;
            v = as.y + ad.y; rv.y = (v > 0.f) ? v : 0.2f * v;
            v = as.z + ad.z; rv.z = (v > 0.f) ? v : 0.2f * v;
            v = as.w + ad.w; rv.w = (v > 0.f) ? v : 0.2f * v;
        }
        float m0 = rv.x, m1 = rv.y, m2 = rv.z, m3 = rv.w;
#pragma unroll
        for (int o = 16; o; o >>= 1) {
            m0 = fmaxf(m0, __shfl_xor_sync(0xFFFFFFFFu, m0, o));
            m1 = fmaxf(m1, __shfl_xor_sync(0xFFFFFFFFu, m1, o));
            m2 = fmaxf(m2, __shfl_xor_sync(0xFFFFFFFFu, m2, o));
            m3 = fmaxf(m3, __shfl_xor_sync(0xFFFFFFFFu, m3, o));
        }
        float4 av = {0.f, 0.f, 0.f, 0.f};
        if (lane < d) {
            av.x = __expf(rv.x - m0);
            av.y = __expf(rv.y - m1);
            av.z = __expf(rv.z - m2);
            av.w = __expf(rv.w - m3);
        }
        float s0 = av.x, s1 = av.y, s2 = av.z, s3 = av.w;
#pragma unroll
        for (int o = 16; o; o >>= 1) {
            s0 += __shfl_xor_sync(0xFFFFFFFFu, s0, o);
            s1 += __shfl_xor_sync(0xFFFFFFFFu, s1, o);
            s2 += __shfl_xor_sync(0xFFFFFFFFu, s2, o);
            s3 += __shfl_xor_sync(0xFFFFFFFFu, s3, o);
        }
        av.x *= 1.f / (s0 + 1e-16f);
        av.y *= 1.f / (s1 + 1e-16f);
        av.z *= 1.f / (s2 + 1e-16f);
        av.w *= 1.f / (s3 + 1e-16f);
        if (lane < d) *(float4*)&alpha[e * 4] = av;

#pragma unroll 8
        for (int li = 0; li < d; li++) {
            int sb  = __shfl_sync(0xFFFFFFFFu, src, li);
            float w0 = __shfl_sync(0xFFFFFFFFu, av.x, li);
            float w1 = __shfl_sync(0xFFFFFFFFu, av.y, li);
            float w2 = __shfl_sync(0xFFFFFFFFu, av.z, li);
            float w3 = __shfl_sync(0xFFFFFFFFu, av.w, li);
            float2 xv = *(const float2*)&x[sb * F_IN + c0];
            a0.x += w0 * xv.x; a0.y += w0 * xv.y;
            a1.x += w1 * xv.x; a1.y += w1 * xv.y;
            a2.x += w2 * xv.x; a2.y += w2 * xv.y;
            a3.x += w3 * xv.x; a3.y += w3 * xv.y;
        }
    } else {
        // slow path (rare): chunked, register-only, 3 passes
        float m0 = -INFINITY, m1 = -INFINITY, m2 = -INFINITY, m3 = -INFINITY;
        for (int i = start + lane; i < end; i += 32) {
            int2 es = g_csr2[i];
            float4 as = *(const float4*)&g_asrc[es.y * HEADS];
            float v, r;
            v = as.x + ad.x; r = (v > 0.f) ? v : 0.2f * v; m0 = fmaxf(m0, r);
            v = as.y + ad.y; r = (v > 0.f) ? v : 0.2f * v; m1 = fmaxf(m1, r);
            v = as.z + ad.z; r = (v > 0.f) ? v : 0.2f * v; m2 = fmaxf(m2, r);
            v = as.w + ad.w; r = (v > 0.f) ? v : 0.2f * v; m3 = fmaxf(m3, r);
        }
#pragma unroll
        for (int o = 16; o; o >>= 1) {
            m0 = fmaxf(m0, __shfl_xor_sync(0xFFFFFFFFu, m0, o));
            m1 = fmaxf(m1, __shfl_xor_sync(0xFFFFFFFFu, m1, o));
            m2 = fmaxf(m2, __shfl_xor_sync(0xFFFFFFFFu, m2, o));
            m3 = fmaxf(m3, __shfl_xor_sync(0xFFFFFFFFu, m3, o));
        }
        float s0 = 0.f, s1 = 0.f, s2 = 0.f, s3 = 0.f;
        for (int i = start + lane; i < end; i += 32) {
            int2 es = g_csr2[i];
            float4 as = *(const float4*)&g_asrc[es.y * HEADS];
            float v, r; float4 ev;
            v = as.x + ad.x; r = (v > 0.f) ? v : 0.2f * v; ev.x = __expf(r - m0); s0 += ev.x;
            v = as.y + ad.y; r = (v > 0.f) ? v : 0.2f * v; ev.y = __expf(r - m1); s1 += ev.y;
            v = as.z + ad.z; r = (v > 0.f) ? v : 0.2f * v; ev.z = __expf(r - m2); s2 += ev.z;
            v = as.w + ad.w; r = (v > 0.f) ? v : 0.2f * v; ev.w = __expf(r - m3); s3 += ev.w;
            *(float4*)&alpha[es.x * 4] = ev;
        }
#pragma unroll
        for (int o = 16; o; o >>= 1) {
            s0 += __shfl_xor_sync(0xFFFFFFFFu, s0, o);
            s1 += __shfl_xor_sync(0xFFFFFFFFu, s1, o);
            s2 += __shfl_xor_sync(0xFFFFFFFFu, s2, o);
            s3 += __shfl_xor_sync(0xFFFFFFFFu, s3, o);
        }
        float i0 = 1.f / (s0 + 1e-16f), i1 = 1.f / (s1 + 1e-16f);
        float i2 = 1.f / (s2 + 1e-16f), i3 = 1.f / (s3 + 1e-16f);
        for (int base = start; base < end; base += 32) {
            int li = base + lane;
            int cl = min(32, end - base);
            int src = 0; float4 av = {0.f, 0.f, 0.f, 0.f};
            if (li < end) {
                int2 es = g_csr2[li];
                src = es.y;
                av = *(float4*)&alpha[es.x * 4];
                av.x *= i0; av.y *= i1; av.z *= i2; av.w *= i3;
                *(float4*)&alpha[es.x * 4] = av;
            }
            for (int k = 0; k < cl; k++) {
                int sb  = __shfl_sync(0xFFFFFFFFu, src, k);
                float w0 = __shfl_sync(0xFFFFFFFFu, av.x, k);
                float w1 = __shfl_sync(0xFFFFFFFFu, av.y, k);
                float w2 = __shfl_sync(0xFFFFFFFFu, av.z, k);
                float w3 = __shfl_sync(0xFFFFFFFFu, av.w, k);
                float2 xv = *(const float2*)&x[sb * F_IN + c0];
                a0.x += w0 * xv.x; a0.y += w0 * xv.y;
                a1.x += w1 * xv.x; a1.y += w1 * xv.y;
                a2.x += w2 * xv.x; a2.y += w2 * xv.y;
                a3.x += w3 * xv.x; a3.y += w3 * xv.y;
            }
        }
    }
    *(float2*)&g_s[n * HC + 0 * 64 + c0] = a0;
    *(float2*)&g_s[n * HC + 1 * 64 + c0] = a1;
    *(float2*)&g_s[n * HC + 2 * 64 + c0] = a2;
    *(float2*)&g_s[n * HC + 3 * 64 + c0] = a3;
}

// ---------------- post-transform + fused GraphNorm stats ----------------
#define PO_NPB 48
__global__ __launch_bounds__(256) void k_post_gn(const float* __restrict__ lin_w,
                                                 const float* __restrict__ gat_bias,
                                                 const int* __restrict__ batch) {
    __shared__ __align__(16) float ss[PO_NPB * HC];   // 48KB
    __shared__ int sb[PO_NPB];
    int j = threadIdx.x;
    float wreg[F_IN];
#pragma unroll
    for (int c = 0; c < F_IN; c++) wreg[c] = lin_w[j * F_IN + c];
    float bj = gat_bias[j];
    int hoff = (j >> 6) * 64;

    int n0 = blockIdx.x * PO_NPB;
    int nmax = min(PO_NPB, N_NODES - n0);
    for (int t = j; t < nmax * HC; t += 256) ss[t] = g_s[n0 * HC + t];
    if (j < nmax) sb[j] = batch[n0 + j];
    __syncthreads();

    float sum = 0.f, sq = 0.f;
    int curg = sb[0];
    for (int nn = 0; nn < nmax; nn++) {
        int g = sb[nn];
        if (g != curg) {
            atomicAdd(&g_mean[curg * HC + j], sum);
            atomicAdd(&g_var[curg * HC + j], sq);
            sum = 0.f; sq = 0.f; curg = g;
        }
        const float4* sp = (const float4*)&ss[nn * HC + hoff];
        float acc = 0.f;
#pragma unroll
        for (int c4 = 0; c4 < F_IN / 4; c4++) {
            float4 v = sp[c4];
            acc += v.x * wreg[4 * c4] + v.y * wreg[4 * c4 + 1]
                 + v.z * wreg[4 * c4 + 2] + v.w * wreg[4 * c4 + 3];
        }
        acc += bj;
        g_x2[(n0 + nn) * HC + j] = acc;
        sum += acc; sq += acc * acc;
    }
    atomicAdd(&g_mean[curg * HC + j], sum);
    atomicAdd(&g_var[curg * HC + j], sq);
}

// ---------------- fused norm-apply + ReLU + gate MLP + pool accumulate ----------------
#define AG_NPB 16
__global__ __launch_bounds__(256) void k_gatepool(const int* __restrict__ batch,
                                                  const float* __restrict__ mscale,
                                                  const float* __restrict__ gw,
                                                  const float* __restrict__ gb,
                                                  const float* __restrict__ att1_w,
                                                  const float* __restrict__ att1_b,
                                                  const float* __restrict__ att2_w,
                                                  const float* __restrict__ att2_b) {
    __shared__ float wsT[HC * 16];                      // [c][k]
    __shared__ __align__(16) float hs[AG_NPB * HC];
    __shared__ float eg[AG_NPB];
    __shared__ int sb[AG_NPB];
    int j = threadIdx.x;
    for (int t = j; t < 16 * HC; t += 256) {
        int k = t >> 8, c = t & 255;
        wsT[c * 16 + k] = att1_w[t];
    }
    int n0 = blockIdx.x * AG_NPB;
    if (j < AG_NPB) sb[j] = batch[n0 + j];
    float msj = mscale[j], wj = gw[j], bj = gb[j];
    __syncthreads();

    int lastg = -1;
    float cA = 0.f, cB = 0.f;
    for (int nn = 0; nn < AG_NPB; nn++) {
        int g = sb[nn];
        if (g != lastg) {
            float cnt = fmaxf((float)(g_ge[g] - g_gs[g]), 1.f);
            float inv = 1.f / cnt;
            float mean = g_mean[g * HC + j] * inv;
            float ex2 = g_var[g * HC + j] * inv;
            float mm = mean * msj;
            float var = ex2 - 2.f * mm * mean + mm * mm;
            cA = wj * rsqrtf(var + 1e-5f);
            cB = bj - cA * mm;
            lastg = g;
        }
        float h = fmaxf(cA * g_x2[(n0 + nn) * HC + j] + cB, 0.f);
        hs[nn * HC + j] = h;
    }
    __syncthreads();

    {
        int nn = j >> 4, k = j & 15;
        float acc = att1_b[k];
        const float4* hp = (const float4*)&hs[nn * HC];
#pragma unroll 8
        for (int c4 = 0; c4 < HC / 4; c4++) {
            float4 v = hp[c4];
            int c = c4 * 4;
            acc += v.x * wsT[c * 16 + k] + v.y * wsT[(c + 1) * 16 + k]
                 + v.z * wsT[(c + 2) * 16 + k] + v.w * wsT[(c + 3) * 16 + k];
        }
        float r = fmaxf(acc, 0.f) * att2_w[k];
#pragma unroll
        for (int o = 8; o; o >>= 1) r += __shfl_xor_sync(0xFFFFFFFFu, r, o);
        if (k == 0) {
            float gate = 1.f / (1.f + __expf(-(r + att2_b[0])));
            eg[nn] = __expf(gate);
        }
    }
    __syncthreads();

    float pacc = 0.f;
    int curg = sb[0];
    for (int nn = 0; nn < AG_NPB; nn++) {
        int g = sb[nn];
        if (g != curg) {
            atomicAdd(&g_pool[curg * HC + j], pacc);
            pacc = 0.f; curg = g;
        }
        pacc += eg[nn] * hs[nn * HC + j];
    }
    atomicAdd(&g_pool[curg * HC + j], pacc);
    if (j < AG_NPB) atomicAdd(&g_gden[sb[j]], eg[j]);
}

// ---------------- head ----------------
__global__ void k_head(const float* __restrict__ fc1_w, const float* __restrict__ fc1_b,
                       const float* __restrict__ out_w, const float* __restrict__ out_b,
                       float* __restrict__ out) {
    int g = blockIdx.x, o = threadIdx.x;  // 128 threads
    float invZ = 1.f / (g_gden[g] + 1e-16f);
    float acc = fc1_b[o];
    const float* p = &g_pool[g * HC];
    const float* w = &fc1_w[o * HC];
#pragma unroll 8
    for (int c = 0; c < HC; c++) acc += p[c] * invZ * w[c];
    acc = fmaxf(acc, 0.f) * out_w[o];
    __shared__ float red[ODIM];
    red[o] = acc;
    __syncthreads();
#pragma unroll
    for (int s = 64; s; s >>= 1) {
        if (o < s) red[o] += red[o + s];
        __syncthreads();
    }
    if (o == 0) out[g] = 1.f / (1.f + __expf(-(red[0] + out_b[0])));
}

// ---------------- launch ----------------
extern "C" void kernel_launch(void* const* d_in, const int* in_sizes, int n_in,
                              void* d_out, int out_size) {
    const float* x        = (const float*)d_in[0];
    const int*   ei       = (const int*)  d_in[1];
    const int*   batch    = (const int*)  d_in[2];
    const float* lin_w    = (const float*)d_in[3];
    const float* att_src  = (const float*)d_in[4];
    const float* att_dst  = (const float*)d_in[5];
    const float* gat_bias = (const float*)d_in[6];
    const float* gn_w     = (const float*)d_in[7];
    const float* gn_b     = (const float*)d_in[8];
    const float* gn_ms    = (const float*)d_in[9];
    const float* fc1_w    = (const float*)d_in[10];
    const float* fc1_b    = (const float*)d_in[11];
    const float* out_w    = (const float*)d_in[12];
    const float* out_b    = (const float*)d_in[13];
    const float* att1_w   = (const float*)d_in[14];
    const float* att1_b   = (const float*)d_in[15];
    const float* att2_w   = (const float*)d_in[16];
    const float* att2_b   = (const float*)d_in[17];

    float* out   = (float*)d_out;
    float* alpha = out + NGRAPH;   // [NTOT, HEADS]

    k_front<<<FR_BLKS, 256>>>(x, ei, batch, lin_w, att_src, att_dst);
    k_scan1<<<NBLK_SCAN, 256>>>();
    k_scan23<<<NBLK_SCAN, 256>>>();
    k_fill<<<(NTOT + 255) / 256, 256>>>(ei);
    k_gat<<<(N_NODES + GAT_WARPS - 1) / GAT_WARPS, 256>>>(x, alpha);
    k_post_gn<<<(N_NODES + PO_NPB - 1) / PO_NPB, 256>>>(lin_w, gat_bias, batch);
    k_gatepool<<<N_NODES / AG_NPB, 256>>>(batch, gn_ms, gn_w, gn_b,
                                          att1_w, att1_b, att2_w, att2_b);
    k_head<<<NGRAPH, ODIM>>>(fc1_w, fc1_b, out_w, out_b, out);
}

// round 13
// speedup vs baseline: 1.7537x; 1.0648x over previous
#include <cuda_runtime.h>
#include <math.h>

#define N_NODES 50000
#define N_EDGES 800000
#define NTOT    850000   // E + N self loops
#define NGRAPH  256
#define F_IN    64
#define HEADS   4
#define HC      256      // HEADS*F_IN
#define ODIM    128
#define NBLK_SCAN 196    // ceil(N_NODES/256)

// ---------------- scratch (device globals; no allocation) ----------------
__device__ float g_s   [N_NODES * HC];    // per-head weighted x sums
__device__ float g_asrc[N_NODES * HEADS];
__device__ float g_adst[N_NODES * HEADS];
__device__ float g_x2  [N_NODES * HC];    // GAT output
__device__ float g_pool[NGRAPH * HC];     // sum exp(gate)*h
__device__ float g_gden[NGRAPH];          // sum exp(gate)
__device__ float g_mean[NGRAPH * HC];     // raw sum of x2
__device__ float g_var [NGRAPH * HC];     // raw sumsq of x2
__device__ float g_wsrc[HC];              // W_h^T att_src_h
__device__ float g_wdst[HC];
__device__ int   g_deg [N_NODES];
__device__ int   g_rowptr[N_NODES + 1];
__device__ int   g_woff[N_NODES];
__device__ int2  g_csr2[NTOT];            // (edge id, src)
__device__ int   g_blk [256];
__device__ int   g_gs  [NGRAPH];
__device__ int   g_ge  [NGRAPH];

// ---------------- init (+ fused prew in last block) ----------------
__global__ void k_init(const float* __restrict__ lin_w,
                       const float* __restrict__ att_src,
                       const float* __restrict__ att_dst) {
    if (blockIdx.x == 256) {
        int t = threadIdx.x;          // t = h*64 + c
        int h = t >> 6, c = t & 63;
        float as = 0.f, ad = 0.f;
        for (int j = 0; j < F_IN; j++) {
            float w = lin_w[(h * F_IN + j) * F_IN + c];
            as += att_src[h * F_IN + j] * w;
            ad += att_dst[h * F_IN + j] * w;
        }
        g_wsrc[t] = as;
        g_wdst[t] = ad;
        return;
    }
    int i = blockIdx.x * blockDim.x + threadIdx.x;
    if (i < N_NODES) g_deg[i] = 0;
    if (i < NGRAPH * HC) { g_mean[i] = 0.f; g_var[i] = 0.f; g_pool[i] = 0.f; }
    if (i < NGRAPH) { g_gs[i] = N_NODES; g_ge[i] = 0; g_gden[i] = 0.f; }
}

// ---------------- front: scores + hist + bounds in one grid ----------------
#define SC_BLKS 6250
#define HI_BLKS 3321
#define BD_BLKS 196
__global__ __launch_bounds__(256) void k_front(const float* __restrict__ x,
                                               const int* __restrict__ ei,
                                               const int* __restrict__ batch) {
    int b = blockIdx.x;
    if (b < SC_BLKS) {
        int warp = threadIdx.x >> 5, lane = threadIdx.x & 31;
        int n = b * 8 + warp;
        if (n >= N_NODES) return;
        float2 xv = *(const float2*)&x[n * F_IN + lane * 2];
        float p0, p1, p2, p3, q0, q1, q2, q3;
        {
            float2 w;
            w = *(const float2*)&g_wsrc[0 * 64 + lane * 2]; p0 = w.x * xv.x + w.y * xv.y;
            w = *(const float2*)&g_wsrc[1 * 64 + lane * 2]; p1 = w.x * xv.x + w.y * xv.y;
            w = *(const float2*)&g_wsrc[2 * 64 + lane * 2]; p2 = w.x * xv.x + w.y * xv.y;
            w = *(const float2*)&g_wsrc[3 * 64 + lane * 2]; p3 = w.x * xv.x + w.y * xv.y;
            w = *(const float2*)&g_wdst[0 * 64 + lane * 2]; q0 = w.x * xv.x + w.y * xv.y;
            w = *(const float2*)&g_wdst[1 * 64 + lane * 2]; q1 = w.x * xv.x + w.y * xv.y;
            w = *(const float2*)&g_wdst[2 * 64 + lane * 2]; q2 = w.x * xv.x + w.y * xv.y;
            w = *(const float2*)&g_wdst[3 * 64 + lane * 2]; q3 = w.x * xv.x + w.y * xv.y;
        }
#pragma unroll
        for (int o = 16; o; o >>= 1) {
            p0 += __shfl_xor_sync(0xFFFFFFFFu, p0, o);
            p1 += __shfl_xor_sync(0xFFFFFFFFu, p1, o);
            p2 += __shfl_xor_sync(0xFFFFFFFFu, p2, o);
            p3 += __shfl_xor_sync(0xFFFFFFFFu, p3, o);
            q0 += __shfl_xor_sync(0xFFFFFFFFu, q0, o);
            q1 += __shfl_xor_sync(0xFFFFFFFFu, q1, o);
            q2 += __shfl_xor_sync(0xFFFFFFFFu, q2, o);
            q3 += __shfl_xor_sync(0xFFFFFFFFu, q3, o);
        }
        if (lane == 0) {
            float4 a = {p0, p1, p2, p3};
            float4 bb = {q0, q1, q2, q3};
            *(float4*)&g_asrc[n * HEADS] = a;
            *(float4*)&g_adst[n * HEADS] = bb;
        }
    } else if (b < SC_BLKS + HI_BLKS) {
        int e = (b - SC_BLKS) * 256 + threadIdx.x;
        if (e >= NTOT) return;
        int dst = (e < N_EDGES) ? ei[N_EDGES + e] : (e - N_EDGES);
        atomicAdd(&g_deg[dst], 1);
    } else {
        int n = (b - SC_BLKS - HI_BLKS) * 256 + threadIdx.x;
        if (n >= N_NODES) return;
        int g = batch[n];
        atomicMin(&g_gs[g], n);
        atomicMax(&g_ge[g], n + 1);
    }
}

// ---------------- CSR scan (2 kernels) ----------------
__global__ void k_scan1() {
    __shared__ int sm[256];
    int b = blockIdx.x, t = threadIdx.x;
    int idx = b * 256 + t;
    int v = (idx < N_NODES) ? g_deg[idx] : 0;
    sm[t] = v;
    __syncthreads();
#pragma unroll
    for (int o = 1; o < 256; o <<= 1) {
        int u = (t >= o) ? sm[t - o] : 0;
        __syncthreads();
        sm[t] += u;
        __syncthreads();
    }
    if (idx < N_NODES) g_rowptr[idx] = sm[t] - v;
    if (t == 255) g_blk[b] = sm[255];
}

__global__ void k_scan23() {
    __shared__ int sm[256];
    int b = blockIdx.x, t = threadIdx.x;
    sm[t] = (t < b) ? g_blk[t] : 0;   // sum of preceding block aggregates
    __syncthreads();
#pragma unroll
    for (int o = 128; o; o >>= 1) {
        if (t < o) sm[t] += sm[t + o];
        __syncthreads();
    }
    int off = sm[0];
    int idx = b * 256 + t;
    if (idx < N_NODES) {
        int r = g_rowptr[idx] + off;
        g_rowptr[idx] = r;
        g_woff[idx] = r;
    }
    if (b == 0 && t == 0) g_rowptr[N_NODES] = NTOT;
}

__global__ void k_fill(const int* __restrict__ ei) {
    int e = blockIdx.x * blockDim.x + threadIdx.x;
    if (e >= NTOT) return;
    int src, dst;
    if (e < N_EDGES) { src = ei[e]; dst = ei[N_EDGES + e]; }
    else             { src = dst = e - N_EDGES; }
    int pos = atomicAdd(&g_woff[dst], 1);
    int2 es; es.x = e; es.y = src;
    g_csr2[pos] = es;
}

// ---------------- fused GAT: warp per dst node, register-resident ----------------
// NOTE: softmax computed WITHOUT max subtraction — scores are bounded (|s| ~ 10)
// so exp cannot overflow, and exp(a)/sum(exp(a)) is mathematically identical.
#define GAT_WARPS 8
__global__ __launch_bounds__(256) void k_gat(const float* __restrict__ x,
                                             float* __restrict__ alpha) {
    int warp = threadIdx.x >> 5;
    int lane = threadIdx.x & 31;
    int n = blockIdx.x * GAT_WARPS + warp;
    if (n >= N_NODES) return;
    int start = g_rowptr[n], end = g_rowptr[n + 1];
    int d = end - start;
    float4 ad = *(const float4*)&g_adst[n * HEADS];
    int c0 = lane * 2;

    float2 a0 = {0.f,0.f}, a1 = {0.f,0.f}, a2 = {0.f,0.f}, a3 = {0.f,0.f};

    if (d <= 32) {
        int e = 0, src = 0;
        float4 av = {0.f, 0.f, 0.f, 0.f};
        if (lane < d) {
            int2 es = g_csr2[start + lane];
            e = es.x; src = es.y;
            float4 as = *(const float4*)&g_asrc[src * HEADS];
            float v, r;
            v = as.x + ad.x; r = (v > 0.f) ? v : 0.2f * v; av.x = __expf(r);
            v = as.y + ad.y; r = (v > 0.f) ? v : 0.2f * v; av.y = __expf(r);
            v = as.z + ad.z; r = (v > 0.f) ? v : 0.2f * v; av.z = __expf(r);
            v = as.w + ad.w; r = (v > 0.f) ? v : 0.2f * v; av.w = __expf(r);
        }
        float s0 = av.x, s1 = av.y, s2 = av.z, s3 = av.w;
#pragma unroll
        for (int o = 16; o; o >>= 1) {
            s0 += __shfl_xor_sync(0xFFFFFFFFu, s0, o);
            s1 += __shfl_xor_sync(0xFFFFFFFFu, s1, o);
            s2 += __shfl_xor_sync(0xFFFFFFFFu, s2, o);
            s3 += __shfl_xor_sync(0xFFFFFFFFu, s3, o);
        }
        av.x *= 1.f / (s0 + 1e-16f);
        av.y *= 1.f / (s1 + 1e-16f);
        av.z *= 1.f / (s2 + 1e-16f);
        av.w *= 1.f / (s3 + 1e-16f);
        if (lane < d) *(float4*)&alpha[e * 4] = av;

#pragma unroll 8
        for (int li = 0; li < d; li++) {
            int sb  = __shfl_sync(0xFFFFFFFFu, src, li);
            float w0 = __shfl_sync(0xFFFFFFFFu, av.x, li);
            float w1 = __shfl_sync(0xFFFFFFFFu, av.y, li);
            float w2 = __shfl_sync(0xFFFFFFFFu, av.z, li);
            float w3 = __shfl_sync(0xFFFFFFFFu, av.w, li);
            float2 xv = *(const float2*)&x[sb * F_IN + c0];
            a0.x += w0 * xv.x; a0.y += w0 * xv.y;
            a1.x += w1 * xv.x; a1.y += w1 * xv.y;
            a2.x += w2 * xv.x; a2.y += w2 * xv.y;
            a3.x += w3 * xv.x; a3.y += w3 * xv.y;
        }
    } else {
        // slow path (rare): 2 passes, no max needed
        float s0 = 0.f, s1 = 0.f, s2 = 0.f, s3 = 0.f;
        for (int i = start + lane; i < end; i += 32) {
            int2 es = g_csr2[i];
            float4 as = *(const float4*)&g_asrc[es.y * HEADS];
            float v, r; float4 ev;
            v = as.x + ad.x; r = (v > 0.f) ? v : 0.2f * v; ev.x = __expf(r); s0 += ev.x;
            v = as.y + ad.y; r = (v > 0.f) ? v : 0.2f * v; ev.y = __expf(r); s1 += ev.y;
            v = as.z + ad.z; r = (v > 0.f) ? v : 0.2f * v; ev.z = __expf(r); s2 += ev.z;
            v = as.w + ad.w; r = (v > 0.f) ? v : 0.2f * v; ev.w = __expf(r); s3 += ev.w;
            *(float4*)&alpha[es.x * 4] = ev;
        }
#pragma unroll
        for (int o = 16; o; o >>= 1) {
            s0 += __shfl_xor_sync(0xFFFFFFFFu, s0, o);
            s1 += __shfl_xor_sync(0xFFFFFFFFu, s1, o);
            s2 += __shfl_xor_sync(0xFFFFFFFFu, s2, o);
            s3 += __shfl_xor_sync(0xFFFFFFFFu, s3, o);
        }
        float i0 = 1.f / (s0 + 1e-16f), i1 = 1.f / (s1 + 1e-16f);
        float i2 = 1.f / (s2 + 1e-16f), i3 = 1.f / (s3 + 1e-16f);
        for (int base = start; base < end; base += 32) {
            int li = base + lane;
            int cl = min(32, end - base);
            int src = 0; float4 av = {0.f, 0.f, 0.f, 0.f};
            if (li < end) {
                int2 es = g_csr2[li];
                src = es.y;
                av = *(float4*)&alpha[es.x * 4];
                av.x *= i0; av.y *= i1; av.z *= i2; av.w *= i3;
                *(float4*)&alpha[es.x * 4] = av;
            }
            for (int k = 0; k < cl; k++) {
                int sb  = __shfl_sync(0xFFFFFFFFu, src, k);
                float w0 = __shfl_sync(0xFFFFFFFFu, av.x, k);
                float w1 = __shfl_sync(0xFFFFFFFFu, av.y, k);
                float w2 = __shfl_sync(0xFFFFFFFFu, av.z, k);
                float w3 = __shfl_sync(0xFFFFFFFFu, av.w, k);
                float2 xv = *(const float2*)&x[sb * F_IN + c0];
                a0.x += w0 * xv.x; a0.y += w0 * xv.y;
                a1.x += w1 * xv.x; a1.y += w1 * xv.y;
                a2.x += w2 * xv.x; a2.y += w2 * xv.y;
                a3.x += w3 * xv.x; a3.y += w3 * xv.y;
            }
        }
    }
    *(float2*)&g_s[n * HC + 0 * 64 + c0] = a0;
    *(float2*)&g_s[n * HC + 1 * 64 + c0] = a1;
    *(float2*)&g_s[n * HC + 2 * 64 + c0] = a2;
    *(float2*)&g_s[n * HC + 3 * 64 + c0] = a3;
}

// ---------------- post-transform + fused GraphNorm stats ----------------
#define PO_NPB 48
__global__ __launch_bounds__(256) void k_post_gn(const float* __restrict__ lin_w,
                                                 const float* __restrict__ gat_bias,
                                                 const int* __restrict__ batch) {
    __shared__ __align__(16) float ss[PO_NPB * HC];   // 48KB
    __shared__ int sb[PO_NPB];
    int j = threadIdx.x;
    float wreg[F_IN];
#pragma unroll
    for (int c = 0; c < F_IN; c++) wreg[c] = lin_w[j * F_IN + c];
    float bj = gat_bias[j];
    int hoff = (j >> 6) * 64;

    int n0 = blockIdx.x * PO_NPB;
    int nmax = min(PO_NPB, N_NODES - n0);
    for (int t = j; t < nmax * HC; t += 256) ss[t] = g_s[n0 * HC + t];
    if (j < nmax) sb[j] = batch[n0 + j];
    __syncthreads();

    float sum = 0.f, sq = 0.f;
    int curg = sb[0];
    for (int nn = 0; nn < nmax; nn++) {
        int g = sb[nn];
        if (g != curg) {
            atomicAdd(&g_mean[curg * HC + j], sum);
            atomicAdd(&g_var[curg * HC + j], sq);
            sum = 0.f; sq = 0.f; curg = g;
        }
        const float4* sp = (const float4*)&ss[nn * HC + hoff];
        float acc = 0.f;
#pragma unroll
        for (int c4 = 0; c4 < F_IN / 4; c4++) {
            float4 v = sp[c4];
            acc += v.x * wreg[4 * c4] + v.y * wreg[4 * c4 + 1]
                 + v.z * wreg[4 * c4 + 2] + v.w * wreg[4 * c4 + 3];
        }
        acc += bj;
        g_x2[(n0 + nn) * HC + j] = acc;
        sum += acc; sq += acc * acc;
    }
    atomicAdd(&g_mean[curg * HC + j], sum);
    atomicAdd(&g_var[curg * HC + j], sq);
}

// ---------------- fused norm-apply + ReLU + gate MLP + pool accumulate ----------------
#define AG_NPB 16
__global__ __launch_bounds__(256) void k_gatepool(const int* __restrict__ batch,
                                                  const float* __restrict__ mscale,
                                                  const float* __restrict__ gw,
                                                  const float* __restrict__ gb,
                                                  const float* __restrict__ att1_w,
                                                  const float* __restrict__ att1_b,
                                                  const float* __restrict__ att2_w,
                                                  const float* __restrict__ att2_b) {
    __shared__ float wsT[HC * 16];                      // [c][k]
    __shared__ __align__(16) float hs[AG_NPB * HC];
    __shared__ float eg[AG_NPB];
    __shared__ int sb[AG_NPB];
    int j = threadIdx.x;
    for (int t = j; t < 16 * HC; t += 256) {
        int k = t >> 8, c = t & 255;
        wsT[c * 16 + k] = att1_w[t];
    }
    int n0 = blockIdx.x * AG_NPB;
    if (j < AG_NPB) sb[j] = batch[n0 + j];
    float msj = mscale[j], wj = gw[j], bj = gb[j];
    __syncthreads();

    int lastg = -1;
    float cA = 0.f, cB = 0.f;
    for (int nn = 0; nn < AG_NPB; nn++) {
        int g = sb[nn];
        if (g != lastg) {
            float cnt = fmaxf((float)(g_ge[g] - g_gs[g]), 1.f);
            float inv = 1.f / cnt;
            float mean = g_mean[g * HC + j] * inv;
            float ex2 = g_var[g * HC + j] * inv;
            float mm = mean * msj;
            float var = ex2 - 2.f * mm * mean + mm * mm;
            cA = wj * rsqrtf(var + 1e-5f);
            cB = bj - cA * mm;
            lastg = g;
        }
        float h = fmaxf(cA * g_x2[(n0 + nn) * HC + j] + cB, 0.f);
        hs[nn * HC + j] = h;
    }
    __syncthreads();

    {
        int nn = j >> 4, k = j & 15;
        float acc = att1_b[k];
        const float4* hp = (const float4*)&hs[nn * HC];
#pragma unroll 8
        for (int c4 = 0; c4 < HC / 4; c4++) {
            float4 v = hp[c4];
            int c = c4 * 4;
            acc += v.x * wsT[c * 16 + k] + v.y * wsT[(c + 1) * 16 + k]
                 + v.z * wsT[(c + 2) * 16 + k] + v.w * wsT[(c + 3) * 16 + k];
        }
        float r = fmaxf(acc, 0.f) * att2_w[k];
#pragma unroll
        for (int o = 8; o; o >>= 1) r += __shfl_xor_sync(0xFFFFFFFFu, r, o);
        if (k == 0) {
            float gate = 1.f / (1.f + __expf(-(r + att2_b[0])));
            eg[nn] = __expf(gate);
        }
    }
    __syncthreads();

    float pacc = 0.f;
    int curg = sb[0];
    for (int nn = 0; nn < AG_NPB; nn++) {
        int g = sb[nn];
        if (g != curg) {
            atomicAdd(&g_pool[curg * HC + j], pacc);
            pacc = 0.f; curg = g;
        }
        pacc += eg[nn] * hs[nn * HC + j];
    }
    atomicAdd(&g_pool[curg * HC + j], pacc);
    if (j < AG_NPB) atomicAdd(&g_gden[sb[j]], eg[j]);
}

// ---------------- head ----------------
__global__ void k_head(const float* __restrict__ fc1_w, const float* __restrict__ fc1_b,
                       const float* __restrict__ out_w, const float* __restrict__ out_b,
                       float* __restrict__ out) {
    int g = blockIdx.x, o = threadIdx.x;  // 128 threads
    float invZ = 1.f / (g_gden[g] + 1e-16f);
    float dot = 0.f;
    const float* p = &g_pool[g * HC];
    const float* w = &fc1_w[o * HC];
#pragma unroll 8
    for (int c = 0; c < HC; c++) dot += p[c] * w[c];
    float acc = fmaxf(fc1_b[o] + invZ * dot, 0.f) * out_w[o];
    __shared__ float red[ODIM];
    red[o] = acc;
    __syncthreads();
#pragma unroll
    for (int s = 64; s; s >>= 1) {
        if (o < s) red[o] += red[o + s];
        __syncthreads();
    }
    if (o == 0) out[g] = 1.f / (1.f + __expf(-(red[0] + out_b[0])));
}

// ---------------- launch ----------------
extern "C" void kernel_launch(void* const* d_in, const int* in_sizes, int n_in,
                              void* d_out, int out_size) {
    const float* x        = (const float*)d_in[0];
    const int*   ei       = (const int*)  d_in[1];
    const int*   batch    = (const int*)  d_in[2];
    const float* lin_w    = (const float*)d_in[3];
    const float* att_src  = (const float*)d_in[4];
    const float* att_dst  = (const float*)d_in[5];
    const float* gat_bias = (const float*)d_in[6];
    const float* gn_w     = (const float*)d_in[7];
    const float* gn_b     = (const float*)d_in[8];
    const float* gn_ms    = (const float*)d_in[9];
    const float* fc1_w    = (const float*)d_in[10];
    const float* fc1_b    = (const float*)d_in[11];
    const float* out_w    = (const float*)d_in[12];
    const float* out_b    = (const float*)d_in[13];
    const float* att1_w   = (const float*)d_in[14];
    const float* att1_b   = (const float*)d_in[15];
    const float* att2_w   = (const float*)d_in[16];
    const float* att2_b   = (const float*)d_in[17];

    float* out   = (float*)d_out;
    float* alpha = out + NGRAPH;   // [NTOT, HEADS]

    k_init<<<257, 256>>>(lin_w, att_src, att_dst);
    k_front<<<SC_BLKS + HI_BLKS + BD_BLKS, 256>>>(x, ei, batch);
    k_scan1<<<NBLK_SCAN, 256>>>();
    k_scan23<<<NBLK_SCAN, 256>>>();
    k_fill<<<(NTOT + 255) / 256, 256>>>(ei);
    k_gat<<<(N_NODES + GAT_WARPS - 1) / GAT_WARPS, 256>>>(x, alpha);
    k_post_gn<<<(N_NODES + PO_NPB - 1) / PO_NPB, 256>>>(lin_w, gat_bias, batch);
    k_gatepool<<<N_NODES / AG_NPB, 256>>>(batch, gn_ms, gn_w, gn_b,
                                          att1_w, att1_b, att2_w, att2_b);
    k_head<<<NGRAPH, ODIM>>>(fc1_w, fc1_b, out_w, out_b, out);
}

// round 14
// speedup vs baseline: 1.8066x; 1.0302x over previous
#include <cuda_runtime.h>
#include <math.h>

#define N_NODES 50000
#define N_EDGES 800000
#define NTOT    850000   // E + N self loops
#define NGRAPH  256
#define F_IN    64
#define HEADS   4
#define HC      256      // HEADS*F_IN
#define ODIM    128
#define NBLK_SCAN 196    // ceil(N_NODES/256)

// ---------------- scratch (device globals; no allocation) ----------------
__device__ float g_s   [N_NODES * HC];    // per-head weighted x sums
__device__ float g_asrc[N_NODES * HEADS];
__device__ float g_adst[N_NODES * HEADS];
__device__ float g_x2  [N_NODES * HC];    // GAT output
__device__ float g_pool[NGRAPH * HC];     // sum exp(gate)*h
__device__ float g_gden[NGRAPH];          // sum exp(gate)
__device__ float g_mean[NGRAPH * HC];     // raw sum of x2
__device__ float g_var [NGRAPH * HC];     // raw sumsq of x2
__device__ float g_wsrc[HC];              // W_h^T att_src_h
__device__ float g_wdst[HC];
__device__ int   g_deg [N_NODES];
__device__ int   g_rowptr[N_NODES + 1];
__device__ int   g_woff[N_NODES];
__device__ int2  g_csr2[NTOT];            // (edge id, src)
__device__ int   g_blk [256];
__device__ int   g_gs  [NGRAPH];
__device__ int   g_ge  [NGRAPH];

// ---------------- init (+ fused prew in last block) ----------------
__global__ void k_init(const float* __restrict__ lin_w,
                       const float* __restrict__ att_src,
                       const float* __restrict__ att_dst) {
    if (blockIdx.x == 256) {
        int t = threadIdx.x;          // t = h*64 + c
        int h = t >> 6, c = t & 63;
        float as = 0.f, ad = 0.f;
        for (int j = 0; j < F_IN; j++) {
            float w = lin_w[(h * F_IN + j) * F_IN + c];
            as += att_src[h * F_IN + j] * w;
            ad += att_dst[h * F_IN + j] * w;
        }
        g_wsrc[t] = as;
        g_wdst[t] = ad;
        return;
    }
    int i = blockIdx.x * blockDim.x + threadIdx.x;
    if (i < N_NODES) g_deg[i] = 0;
    if (i < NGRAPH * HC) { g_mean[i] = 0.f; g_var[i] = 0.f; g_pool[i] = 0.f; }
    if (i < NGRAPH) { g_gs[i] = N_NODES; g_ge[i] = 0; g_gden[i] = 0.f; }
}

// ---------------- front: scores + hist + bounds in one grid ----------------
#define SC_BLKS 6250
#define HI_BLKS 3321
#define BD_BLKS 196
__global__ __launch_bounds__(256) void k_front(const float* __restrict__ x,
                                               const int* __restrict__ ei,
                                               const int* __restrict__ batch) {
    int b = blockIdx.x;
    if (b < SC_BLKS) {
        int warp = threadIdx.x >> 5, lane = threadIdx.x & 31;
        int n = b * 8 + warp;
        if (n >= N_NODES) return;
        float2 xv = *(const float2*)&x[n * F_IN + lane * 2];
        float p0, p1, p2, p3, q0, q1, q2, q3;
        {
            float2 w;
            w = *(const float2*)&g_wsrc[0 * 64 + lane * 2]; p0 = w.x * xv.x + w.y * xv.y;
            w = *(const float2*)&g_wsrc[1 * 64 + lane * 2]; p1 = w.x * xv.x + w.y * xv.y;
            w = *(const float2*)&g_wsrc[2 * 64 + lane * 2]; p2 = w.x * xv.x + w.y * xv.y;
            w = *(const float2*)&g_wsrc[3 * 64 + lane * 2]; p3 = w.x * xv.x + w.y * xv.y;
            w = *(const float2*)&g_wdst[0 * 64 + lane * 2]; q0 = w.x * xv.x + w.y * xv.y;
            w = *(const float2*)&g_wdst[1 * 64 + lane * 2]; q1 = w.x * xv.x + w.y * xv.y;
            w = *(const float2*)&g_wdst[2 * 64 + lane * 2]; q2 = w.x * xv.x + w.y * xv.y;
            w = *(const float2*)&g_wdst[3 * 64 + lane * 2]; q3 = w.x * xv.x + w.y * xv.y;
        }
#pragma unroll
        for (int o = 16; o; o >>= 1) {
            p0 += __shfl_xor_sync(0xFFFFFFFFu, p0, o);
            p1 += __shfl_xor_sync(0xFFFFFFFFu, p1, o);
            p2 += __shfl_xor_sync(0xFFFFFFFFu, p2, o);
            p3 += __shfl_xor_sync(0xFFFFFFFFu, p3, o);
            q0 += __shfl_xor_sync(0xFFFFFFFFu, q0, o);
            q1 += __shfl_xor_sync(0xFFFFFFFFu, q1, o);
            q2 += __shfl_xor_sync(0xFFFFFFFFu, q2, o);
            q3 += __shfl_xor_sync(0xFFFFFFFFu, q3, o);
        }
        if (lane == 0) {
            float4 a = {p0, p1, p2, p3};
            float4 bb = {q0, q1, q2, q3};
            *(float4*)&g_asrc[n * HEADS] = a;
            *(float4*)&g_adst[n * HEADS] = bb;
        }
    } else if (b < SC_BLKS + HI_BLKS) {
        int e = (b - SC_BLKS) * 256 + threadIdx.x;
        if (e >= NTOT) return;
        int dst = (e < N_EDGES) ? ei[N_EDGES + e] : (e - N_EDGES);
        atomicAdd(&g_deg[dst], 1);
    } else {
        int n = (b - SC_BLKS - HI_BLKS) * 256 + threadIdx.x;
        if (n >= N_NODES) return;
        int g = batch[n];
        atomicMin(&g_gs[g], n);
        atomicMax(&g_ge[g], n + 1);
    }
}

// ---------------- CSR scan (2 kernels) ----------------
__global__ void k_scan1() {
    __shared__ int sm[256];
    int b = blockIdx.x, t = threadIdx.x;
    int idx = b * 256 + t;
    int v = (idx < N_NODES) ? g_deg[idx] : 0;
    sm[t] = v;
    __syncthreads();
#pragma unroll
    for (int o = 1; o < 256; o <<= 1) {
        int u = (t >= o) ? sm[t - o] : 0;
        __syncthreads();
        sm[t] += u;
        __syncthreads();
    }
    if (idx < N_NODES) g_rowptr[idx] = sm[t] - v;
    if (t == 255) g_blk[b] = sm[255];
}

__global__ void k_scan23() {
    __shared__ int sm[256];
    int b = blockIdx.x, t = threadIdx.x;
    sm[t] = (t < b) ? g_blk[t] : 0;   // sum of preceding block aggregates
    __syncthreads();
#pragma unroll
    for (int o = 128; o; o >>= 1) {
        if (t < o) sm[t] += sm[t + o];
        __syncthreads();
    }
    int off = sm[0];
    int idx = b * 256 + t;
    if (idx < N_NODES) {
        int r = g_rowptr[idx] + off;
        g_rowptr[idx] = r;
        g_woff[idx] = r;
    }
    if (b == 0 && t == 0) g_rowptr[N_NODES] = NTOT;
}

__global__ void k_fill(const int* __restrict__ ei) {
    int e = blockIdx.x * blockDim.x + threadIdx.x;
    if (e >= NTOT) return;
    int src, dst;
    if (e < N_EDGES) { src = ei[e]; dst = ei[N_EDGES + e]; }
    else             { src = dst = e - N_EDGES; }
    int pos = atomicAdd(&g_woff[dst], 1);
    int2 es; es.x = e; es.y = src;
    g_csr2[pos] = es;
}

// ---------------- fused GAT: warp per dst node, register-resident ----------------
#define GAT_WARPS 8
__global__ __launch_bounds__(256) void k_gat(const float* __restrict__ x,
                                             float* __restrict__ alpha) {
    int warp = threadIdx.x >> 5;
    int lane = threadIdx.x & 31;
    int n = blockIdx.x * GAT_WARPS + warp;
    if (n >= N_NODES) return;
    int start = g_rowptr[n], end = g_rowptr[n + 1];
    int d = end - start;
    float4 ad = *(const float4*)&g_adst[n * HEADS];
    int c0 = lane * 2;

    float2 a0 = {0.f,0.f}, a1 = {0.f,0.f}, a2 = {0.f,0.f}, a3 = {0.f,0.f};

    if (d <= 32) {
        int e = 0, src = 0;
        float4 rv = {-INFINITY, -INFINITY, -INFINITY, -INFINITY};
        if (lane < d) {
            int2 es = g_csr2[start + lane];
            e = es.x; src = es.y;
            float4 as = *(const float4*)&g_asrc[src * HEADS];
            float v;
            v = as.x + ad.x; rv.x = (v > 0.f) ? v : 0.2f * v;
            v = as.y + ad.y; rv.y = (v > 0.f) ? v : 0.2f * v;
            v = as.z + ad.z; rv.z = (v > 0.f) ? v : 0.2f * v;
            v = as.w + ad.w; rv.w = (v > 0.f) ? v : 0.2f * v;
        }
        float m0 = rv.x, m1 = rv.y, m2 = rv.z, m3 = rv.w;
#pragma unroll
        for (int o = 16; o; o >>= 1) {
            m0 = fmaxf(m0, __shfl_xor_sync(0xFFFFFFFFu, m0, o));
            m1 = fmaxf(m1, __shfl_xor_sync(0xFFFFFFFFu, m1, o));
            m2 = fmaxf(m2, __shfl_xor_sync(0xFFFFFFFFu, m2, o));
            m3 = fmaxf(m3, __shfl_xor_sync(0xFFFFFFFFu, m3, o));
        }
        float4 av = {0.f, 0.f, 0.f, 0.f};
        if (lane < d) {
            av.x = __expf(rv.x - m0);
            av.y = __expf(rv.y - m1);
            av.z = __expf(rv.z - m2);
            av.w = __expf(rv.w - m3);
        }
        float s0 = av.x, s1 = av.y, s2 = av.z, s3 = av.w;
#pragma unroll
        for (int o = 16; o; o >>= 1) {
            s0 += __shfl_xor_sync(0xFFFFFFFFu, s0, o);
            s1 += __shfl_xor_sync(0xFFFFFFFFu, s1, o);
            s2 += __shfl_xor_sync(0xFFFFFFFFu, s2, o);
            s3 += __shfl_xor_sync(0xFFFFFFFFu, s3, o);
        }
        av.x *= 1.f / (s0 + 1e-16f);
        av.y *= 1.f / (s1 + 1e-16f);
        av.z *= 1.f / (s2 + 1e-16f);
        av.w *= 1.f / (s3 + 1e-16f);
        if (lane < d) *(float4*)&alpha[e * 4] = av;

#pragma unroll 8
        for (int li = 0; li < d; li++) {
            int sb  = __shfl_sync(0xFFFFFFFFu, src, li);
            float w0 = __shfl_sync(0xFFFFFFFFu, av.x, li);
            float w1 = __shfl_sync(0xFFFFFFFFu, av.y, li);
            float w2 = __shfl_sync(0xFFFFFFFFu, av.z, li);
            float w3 = __shfl_sync(0xFFFFFFFFu, av.w, li);
            float2 xv = *(const float2*)&x[sb * F_IN + c0];
            a0.x += w0 * xv.x; a0.y += w0 * xv.y;
            a1.x += w1 * xv.x; a1.y += w1 * xv.y;
            a2.x += w2 * xv.x; a2.y += w2 * xv.y;
            a3.x += w3 * xv.x; a3.y += w3 * xv.y;
        }
    } else {
        // slow path (rare): chunked, register-only, 3 passes
        float m0 = -INFINITY, m1 = -INFINITY, m2 = -INFINITY, m3 = -INFINITY;
        for (int i = start + lane; i < end; i += 32) {
            int2 es = g_csr2[i];
            float4 as = *(const float4*)&g_asrc[es.y * HEADS];
            float v, r;
            v = as.x + ad.x; r = (v > 0.f) ? v : 0.2f * v; m0 = fmaxf(m0, r);
            v = as.y + ad.y; r = (v > 0.f) ? v : 0.2f * v; m1 = fmaxf(m1, r);
            v = as.z + ad.z; r = (v > 0.f) ? v : 0.2f * v; m2 = fmaxf(m2, r);
            v = as.w + ad.w; r = (v > 0.f) ? v : 0.2f * v; m3 = fmaxf(m3, r);
        }
#pragma unroll
        for (int o = 16; o; o >>= 1) {
            m0 = fmaxf(m0, __shfl_xor_sync(0xFFFFFFFFu, m0, o));
            m1 = fmaxf(m1, __shfl_xor_sync(0xFFFFFFFFu, m1, o));
            m2 = fmaxf(m2, __shfl_xor_sync(0xFFFFFFFFu, m2, o));
            m3 = fmaxf(m3, __shfl_xor_sync(0xFFFFFFFFu, m3, o));
        }
        float s0 = 0.f, s1 = 0.f, s2 = 0.f, s3 = 0.f;
        for (int i = start + lane; i < end; i += 32) {
            int2 es = g_csr2[i];
            float4 as = *(const float4*)&g_asrc[es.y * HEADS];
            float v, r; float4 ev;
            v = as.x + ad.x; r = (v > 0.f) ? v : 0.2f * v; ev.x = __expf(r - m0); s0 += ev.x;
            v = as.y + ad.y; r = (v > 0.f) ? v : 0.2f * v; ev.y = __expf(r - m1); s1 += ev.y;
            v = as.z + ad.z; r = (v > 0.f) ? v : 0.2f * v; ev.z = __expf(r - m2); s2 += ev.z;
            v = as.w + ad.w; r = (v > 0.f) ? v : 0.2f * v; ev.w = __expf(r - m3); s3 += ev.w;
            *(float4*)&alpha[es.x * 4] = ev;
        }
#pragma unroll
        for (int o = 16; o; o >>= 1) {
            s0 += __shfl_xor_sync(0xFFFFFFFFu, s0, o);
            s1 += __shfl_xor_sync(0xFFFFFFFFu, s1, o);
            s2 += __shfl_xor_sync(0xFFFFFFFFu, s2, o);
            s3 += __shfl_xor_sync(0xFFFFFFFFu, s3, o);
        }
        float i0 = 1.f / (s0 + 1e-16f), i1 = 1.f / (s1 + 1e-16f);
        float i2 = 1.f / (s2 + 1e-16f), i3 = 1.f / (s3 + 1e-16f);
        for (int base = start; base < end; base += 32) {
            int li = base + lane;
            int cl = min(32, end - base);
            int src = 0; float4 av = {0.f, 0.f, 0.f, 0.f};
            if (li < end) {
                int2 es = g_csr2[li];
                src = es.y;
                av = *(float4*)&alpha[es.x * 4];
                av.x *= i0; av.y *= i1; av.z *= i2; av.w *= i3;
                *(float4*)&alpha[es.x * 4] = av;
            }
            for (int k = 0; k < cl; k++) {
                int sb  = __shfl_sync(0xFFFFFFFFu, src, k);
                float w0 = __shfl_sync(0xFFFFFFFFu, av.x, k);
                float w1 = __shfl_sync(0xFFFFFFFFu, av.y, k);
                float w2 = __shfl_sync(0xFFFFFFFFu, av.z, k);
                float w3 = __shfl_sync(0xFFFFFFFFu, av.w, k);
                float2 xv = *(const float2*)&x[sb * F_IN + c0];
                a0.x += w0 * xv.x; a0.y += w0 * xv.y;
                a1.x += w1 * xv.x; a1.y += w1 * xv.y;
                a2.x += w2 * xv.x; a2.y += w2 * xv.y;
                a3.x += w3 * xv.x; a3.y += w3 * xv.y;
            }
        }
    }
    *(float2*)&g_s[n * HC + 0 * 64 + c0] = a0;
    *(float2*)&g_s[n * HC + 1 * 64 + c0] = a1;
    *(float2*)&g_s[n * HC + 2 * 64 + c0] = a2;
    *(float2*)&g_s[n * HC + 3 * 64 + c0] = a3;
}

// ---------------- post-transform + fused GraphNorm stats ----------------
#define PO_NPB 48
__global__ __launch_bounds__(256) void k_post_gn(const float* __restrict__ lin_w,
                                                 const float* __restrict__ gat_bias,
                                                 const int* __restrict__ batch) {
    __shared__ __align__(16) float ss[PO_NPB * HC];   // 48KB
    __shared__ int sb[PO_NPB];
    int j = threadIdx.x;
    float wreg[F_IN];
#pragma unroll
    for (int c = 0; c < F_IN; c++) wreg[c] = lin_w[j * F_IN + c];
    float bj = gat_bias[j];
    int hoff = (j >> 6) * 64;

    int n0 = blockIdx.x * PO_NPB;
    int nmax = min(PO_NPB, N_NODES - n0);
    for (int t = j; t < nmax * HC; t += 256) ss[t] = g_s[n0 * HC + t];
    if (j < nmax) sb[j] = batch[n0 + j];
    __syncthreads();

    float sum = 0.f, sq = 0.f;
    int curg = sb[0];
    for (int nn = 0; nn < nmax; nn++) {
        int g = sb[nn];
        if (g != curg) {
            atomicAdd(&g_mean[curg * HC + j], sum);
            atomicAdd(&g_var[curg * HC + j], sq);
            sum = 0.f; sq = 0.f; curg = g;
        }
        const float4* sp = (const float4*)&ss[nn * HC + hoff];
        float acc = 0.f;
#pragma unroll
        for (int c4 = 0; c4 < F_IN / 4; c4++) {
            float4 v = sp[c4];
            acc += v.x * wreg[4 * c4] + v.y * wreg[4 * c4 + 1]
                 + v.z * wreg[4 * c4 + 2] + v.w * wreg[4 * c4 + 3];
        }
        acc += bj;
        g_x2[(n0 + nn) * HC + j] = acc;
        sum += acc; sq += acc * acc;
    }
    atomicAdd(&g_mean[curg * HC + j], sum);
    atomicAdd(&g_var[curg * HC + j], sq);
}

// ---------------- fused norm-apply + ReLU + gate MLP + pool accumulate ----------------
#define AG_NPB 16
__global__ __launch_bounds__(256) void k_gatepool(const int* __restrict__ batch,
                                                  const float* __restrict__ mscale,
                                                  const float* __restrict__ gw,
                                                  const float* __restrict__ gb,
                                                  const float* __restrict__ att1_w,
                                                  const float* __restrict__ att1_b,
                                                  const float* __restrict__ att2_w,
                                                  const float* __restrict__ att2_b) {
    __shared__ float wsT[HC * 16];                      // [c][k]
    __shared__ __align__(16) float hs[AG_NPB * HC];
    __shared__ float eg[AG_NPB];
    __shared__ int sb[AG_NPB];
    int j = threadIdx.x;
    for (int t = j; t < 16 * HC; t += 256) {
        int k = t >> 8, c = t & 255;
        wsT[c * 16 + k] = att1_w[t];
    }
    int n0 = blockIdx.x * AG_NPB;
    if (j < AG_NPB) sb[j] = batch[n0 + j];
    float msj = mscale[j], wj = gw[j], bj = gb[j];
    __syncthreads();

    int lastg = -1;
    float cA = 0.f, cB = 0.f;
    for (int nn = 0; nn < AG_NPB; nn++) {
        int g = sb[nn];
        if (g != lastg) {
            float cnt = fmaxf((float)(g_ge[g] - g_gs[g]), 1.f);
            float inv = 1.f / cnt;
            float mean = g_mean[g * HC + j] * inv;
            float ex2 = g_var[g * HC + j] * inv;
            float mm = mean * msj;
            float var = ex2 - 2.f * mm * mean + mm * mm;
            cA = wj * rsqrtf(var + 1e-5f);
            cB = bj - cA * mm;
            lastg = g;
        }
        float h = fmaxf(cA * g_x2[(n0 + nn) * HC + j] + cB, 0.f);
        hs[nn * HC + j] = h;
    }
    __syncthreads();

    {
        int nn = j >> 4, k = j & 15;
        float acc = att1_b[k];
        const float4* hp = (const float4*)&hs[nn * HC];
#pragma unroll 8
        for (int c4 = 0; c4 < HC / 4; c4++) {
            float4 v = hp[c4];
            int c = c4 * 4;
            acc += v.x * wsT[c * 16 + k] + v.y * wsT[(c + 1) * 16 + k]
                 + v.z * wsT[(c + 2) * 16 + k] + v.w * wsT[(c + 3) * 16 + k];
        }
        float r = fmaxf(acc, 0.f) * att2_w[k];
#pragma unroll
        for (int o = 8; o; o >>= 1) r += __shfl_xor_sync(0xFFFFFFFFu, r, o);
        if (k == 0) {
            float gate = 1.f / (1.f + __expf(-(r + att2_b[0])));
            eg[nn] = __expf(gate);
        }
    }
    __syncthreads();

    float pacc = 0.f;
    int curg = sb[0];
    for (int nn = 0; nn < AG_NPB; nn++) {
        int g = sb[nn];
        if (g != curg) {
            atomicAdd(&g_pool[curg * HC + j], pacc);
            pacc = 0.f; curg = g;
        }
        pacc += eg[nn] * hs[nn * HC + j];
    }
    atomicAdd(&g_pool[curg * HC + j], pacc);
    if (j < AG_NPB) atomicAdd(&g_gden[sb[j]], eg[j]);
}

// ---------------- head ----------------
__global__ void k_head(const float* __restrict__ fc1_w, const float* __restrict__ fc1_b,
                       const float* __restrict__ out_w, const float* __restrict__ out_b,
                       float* __restrict__ out) {
    int g = blockIdx.x, o = threadIdx.x;  // 128 threads
    float invZ = 1.f / (g_gden[g] + 1e-16f);
    float acc = fc1_b[o];
    const float* p = &g_pool[g * HC];
    const float* w = &fc1_w[o * HC];
#pragma unroll 8
    for (int c = 0; c < HC; c++) acc += p[c] * invZ * w[c];
    acc = fmaxf(acc, 0.f) * out_w[o];
    __shared__ float red[ODIM];
    red[o] = acc;
    __syncthreads();
#pragma unroll
    for (int s = 64; s; s >>= 1) {
        if (o < s) red[o] += red[o + s];
        __syncthreads();
    }
    if (o == 0) out[g] = 1.f / (1.f + __expf(-(red[0] + out_b[0])));
}

// ---------------- launch ----------------
extern "C" void kernel_launch(void* const* d_in, const int* in_sizes, int n_in,
                              void* d_out, int out_size) {
    const float* x        = (const float*)d_in[0];
    const int*   ei       = (const int*)  d_in[1];
    const int*   batch    = (const int*)  d_in[2];
    const float* lin_w    = (const float*)d_in[3];
    const float* att_src  = (const float*)d_in[4];
    const float* att_dst  = (const float*)d_in[5];
    const float* gat_bias = (const float*)d_in[6];
    const float* gn_w     = (const float*)d_in[7];
    const float* gn_b     = (const float*)d_in[8];
    const float* gn_ms    = (const float*)d_in[9];
    const float* fc1_w    = (const float*)d_in[10];
    const float* fc1_b    = (const float*)d_in[11];
    const float* out_w    = (const float*)d_in[12];
    const float* out_b    = (const float*)d_in[13];
    const float* att1_w   = (const float*)d_in[14];
    const float* att1_b   = (const float*)d_in[15];
    const float* att2_w   = (const float*)d_in[16];
    const float* att2_b   = (const float*)d_in[17];

    float* out   = (float*)d_out;
    float* alpha = out + NGRAPH;   // [NTOT, HEADS]

    k_init<<<257, 256>>>(lin_w, att_src, att_dst);
    k_front<<<SC_BLKS + HI_BLKS + BD_BLKS, 256>>>(x, ei, batch);
    k_scan1<<<NBLK_SCAN, 256>>>();
    k_scan23<<<NBLK_SCAN, 256>>>();
    k_fill<<<(NTOT + 255) / 256, 256>>>(ei);
    k_gat<<<(N_NODES + GAT_WARPS - 1) / GAT_WARPS, 256>>>(x, alpha);
    k_post_gn<<<(N_NODES + PO_NPB - 1) / PO_NPB, 256>>>(lin_w, gat_bias, batch);
    k_gatepool<<<N_NODES / AG_NPB, 256>>>(batch, gn_ms, gn_w, gn_b,
                                          att1_w, att1_b, att2_w, att2_b);
    k_head<<<NGRAPH, ODIM>>>(fc1_w, fc1_b, out_w, out_b, out);
}

// round 16
// speedup vs baseline: 1.8685x; 1.0342x over previous
#include <cuda_runtime.h>
#include <math.h>

#define N_NODES 50000
#define N_EDGES 800000
#define NTOT    850000   // E + N self loops
#define NGRAPH  256
#define F_IN    64
#define HEADS   4
#define HC      256      // HEADS*F_IN
#define ODIM    128
#define NBLK_SCAN 196    // ceil(N_NODES/256)

// ---------------- scratch (device globals; no allocation) ----------------
// NOTE: zero-initialized at load; g_deg and the stats arrays are re-zeroed
// mid-pipeline (in k_fill's extra blocks) so every replay starts clean.
// __align__(16) is REQUIRED on every array accessed through float2/float4/int4.
__device__ __align__(16) float g_s   [N_NODES * HC];    // per-head weighted x sums
__device__ __align__(16) float g_asrc[N_NODES * HEADS];
__device__ __align__(16) float g_adst[N_NODES * HEADS];
__device__ __align__(16) float g_x2  [N_NODES * HC];    // GAT output
__device__ __align__(16) float g_pool[NGRAPH * HC];     // sum exp(gate)*h
__device__ float g_gden[NGRAPH];                        // sum exp(gate)
__device__ __align__(16) float g_mean[NGRAPH * HC];     // raw sum of x2
__device__ __align__(16) float g_var [NGRAPH * HC];     // raw sumsq of x2
__device__ __align__(16) float g_wsrc[HC];              // W_h^T att_src_h
__device__ __align__(16) float g_wdst[HC];
__device__ __align__(16) int   g_deg [N_NODES];
__device__ int   g_rowptr[N_NODES + 1];
__device__ int   g_woff[N_NODES];
__device__ __align__(16) int2  g_csr2[NTOT];            // (edge id, src)
__device__ int   g_gs  [NGRAPH];
__device__ int   g_ge  [NGRAPH];

// ---------------- prew: projected attention vectors (1 block) ----------------
__global__ void k_prew(const float* __restrict__ lin_w,
                       const float* __restrict__ att_src,
                       const float* __restrict__ att_dst) {
    int t = threadIdx.x;          // t = h*64 + c
    int h = t >> 6, c = t & 63;
    float as = 0.f, ad = 0.f;
    for (int j = 0; j < F_IN; j++) {
        float w = lin_w[(h * F_IN + j) * F_IN + c];
        as += att_src[h * F_IN + j] * w;
        ad += att_dst[h * F_IN + j] * w;
    }
    g_wsrc[t] = as;
    g_wdst[t] = ad;
}

// ---------------- front: scores + hist + bounds in one grid ----------------
#define SC_BLKS 6250
#define HI_BLKS 3321
#define BD_BLKS 196
__global__ __launch_bounds__(256) void k_front(const float* __restrict__ x,
                                               const int* __restrict__ ei,
                                               const int* __restrict__ batch) {
    int b = blockIdx.x;
    if (b < SC_BLKS) {
        int warp = threadIdx.x >> 5, lane = threadIdx.x & 31;
        int n = b * 8 + warp;
        if (n >= N_NODES) return;
        float2 xv = *(const float2*)&x[n * F_IN + lane * 2];
        float p0, p1, p2, p3, q0, q1, q2, q3;
        {
            float2 w;
            w = *(const float2*)&g_wsrc[0 * 64 + lane * 2]; p0 = w.x * xv.x + w.y * xv.y;
            w = *(const float2*)&g_wsrc[1 * 64 + lane * 2]; p1 = w.x * xv.x + w.y * xv.y;
            w = *(const float2*)&g_wsrc[2 * 64 + lane * 2]; p2 = w.x * xv.x + w.y * xv.y;
            w = *(const float2*)&g_wsrc[3 * 64 + lane * 2]; p3 = w.x * xv.x + w.y * xv.y;
            w = *(const float2*)&g_wdst[0 * 64 + lane * 2]; q0 = w.x * xv.x + w.y * xv.y;
            w = *(const float2*)&g_wdst[1 * 64 + lane * 2]; q1 = w.x * xv.x + w.y * xv.y;
            w = *(const float2*)&g_wdst[2 * 64 + lane * 2]; q2 = w.x * xv.x + w.y * xv.y;
            w = *(const float2*)&g_wdst[3 * 64 + lane * 2]; q3 = w.x * xv.x + w.y * xv.y;
        }
#pragma unroll
        for (int o = 16; o; o >>= 1) {
            p0 += __shfl_xor_sync(0xFFFFFFFFu, p0, o);
            p1 += __shfl_xor_sync(0xFFFFFFFFu, p1, o);
            p2 += __shfl_xor_sync(0xFFFFFFFFu, p2, o);
            p3 += __shfl_xor_sync(0xFFFFFFFFu, p3, o);
            q0 += __shfl_xor_sync(0xFFFFFFFFu, q0, o);
            q1 += __shfl_xor_sync(0xFFFFFFFFu, q1, o);
            q2 += __shfl_xor_sync(0xFFFFFFFFu, q2, o);
            q3 += __shfl_xor_sync(0xFFFFFFFFu, q3, o);
        }
        if (lane == 0) {
            float4 a = {p0, p1, p2, p3};
            float4 bb = {q0, q1, q2, q3};
            *(float4*)&g_asrc[n * HEADS] = a;
            *(float4*)&g_adst[n * HEADS] = bb;
        }
    } else if (b < SC_BLKS + HI_BLKS) {
        int e = (b - SC_BLKS) * 256 + threadIdx.x;
        if (e >= NTOT) return;
        int dst = (e < N_EDGES) ? ei[N_EDGES + e] : (e - N_EDGES);
        atomicAdd(&g_deg[dst], 1);
    } else {
        // bounds via sorted-neighbor compare (no init needed)
        int n = (b - SC_BLKS - HI_BLKS) * 256 + threadIdx.x;
        if (n >= N_NODES) return;
        int g = batch[n];
        if (n == 0 || batch[n - 1] != g) g_gs[g] = n;
        if (n == N_NODES - 1 || batch[n + 1] != g) g_ge[g] = n + 1;
    }
}

// ---------------- CSR scan: single kernel; each block computes its own prefix ----------------
__global__ __launch_bounds__(256) void k_scan() {
    __shared__ int sm[256];
    __shared__ int wsum[8];
    int b = blockIdx.x, t = threadIdx.x;
    int lane = t & 31, warp = t >> 5;

    // per-thread partial of sum(g_deg[0 .. b*256)) via int4
    int pre = 0;
    const int4* d4 = (const int4*)g_deg;
    int n4 = b * 64;                       // b*256 ints = b*64 int4s
    for (int i = t; i < n4; i += 256) {
        int4 v = d4[i];
        pre += v.x + v.y + v.z + v.w;
    }
#pragma unroll
    for (int o = 16; o; o >>= 1) pre += __shfl_xor_sync(0xFFFFFFFFu, pre, o);
    if (lane == 0) wsum[warp] = pre;

    // inclusive block scan of own 256 degrees
    int idx = b * 256 + t;
    int v = (idx < N_NODES) ? g_deg[idx] : 0;
    sm[t] = v;
    __syncthreads();
#pragma unroll
    for (int o = 1; o < 256; o <<= 1) {
        int u = (t >= o) ? sm[t - o] : 0;
        __syncthreads();
        sm[t] += u;
        __syncthreads();
    }
    int tot = wsum[0] + wsum[1] + wsum[2] + wsum[3]
            + wsum[4] + wsum[5] + wsum[6] + wsum[7];
    if (idx < N_NODES) {
        int r = tot + sm[t] - v;           // exclusive global prefix
        g_rowptr[idx] = r;
        g_woff[idx] = r;
    }
    if (b == 0 && t == 0) g_rowptr[N_NODES] = NTOT;
}

// ---------------- fill CSR (+ self-clean zeroing in extra blocks) ----------------
#define FI_BLKS 3321
#define ZR_BLKS 257
__global__ void k_fill(const int* __restrict__ ei) {
    int b = blockIdx.x;
    if (b >= FI_BLKS) {
        int i = (b - FI_BLKS) * 256 + threadIdx.x;
        if (i < N_NODES) g_deg[i] = 0;
        if (i < NGRAPH * HC) { g_mean[i] = 0.f; g_var[i] = 0.f; g_pool[i] = 0.f; }
        if (i < NGRAPH) g_gden[i] = 0.f;
        return;
    }
    int e = b * 256 + threadIdx.x;
    if (e >= NTOT) return;
    int src, dst;
    if (e < N_EDGES) { src = ei[e]; dst = ei[N_EDGES + e]; }
    else             { src = dst = e - N_EDGES; }
    int pos = atomicAdd(&g_woff[dst], 1);
    int2 es; es.x = e; es.y = src;
    g_csr2[pos] = es;
}

// ---------------- fused GAT: warp per dst node, register-resident ----------------
#define GAT_WARPS 8
__global__ __launch_bounds__(256) void k_gat(const float* __restrict__ x,
                                             float* __restrict__ alpha) {
    int warp = threadIdx.x >> 5;
    int lane = threadIdx.x & 31;
    int n = blockIdx.x * GAT_WARPS + warp;
    if (n >= N_NODES) return;
    int start = g_rowptr[n], end = g_rowptr[n + 1];
    int d = end - start;
    float4 ad = *(const float4*)&g_adst[n * HEADS];
    int c0 = lane * 2;

    float2 a0 = {0.f,0.f}, a1 = {0.f,0.f}, a2 = {0.f,0.f}, a3 = {0.f,0.f};

    if (d <= 32) {
        int e = 0, src = 0;
        float4 rv = {-INFINITY, -INFINITY, -INFINITY, -INFINITY};
        if (lane < d) {
            int2 es = g_csr2[start + lane];
            e = es.x; src = es.y;
            float4 as = *(const float4*)&g_asrc[src * HEADS];
            float v;
            v = as.x + ad.x; rv.x = (v > 0.f) ? v : 0.2f * v;
            v = as.y + ad.y; rv.y = (v > 0.f) ? v : 0.2f * v;
            v = as.z + ad.z; rv.z = (v > 0.f) ? v : 0.2f * v;
            v = as.w + ad.w; rv.w = (v > 0.f) ? v : 0.2f * v;
        }
        float m0 = rv.x, m1 = rv.y, m2 = rv.z, m3 = rv.w;
#pragma unroll
        for (int o = 16; o; o >>= 1) {
            m0 = fmaxf(m0, __shfl_xor_sync(0xFFFFFFFFu, m0, o));
            m1 = fmaxf(m1, __shfl_xor_sync(0xFFFFFFFFu, m1, o));
            m2 = fmaxf(m2, __shfl_xor_sync(0xFFFFFFFFu, m2, o));
            m3 = fmaxf(m3, __shfl_xor_sync(0xFFFFFFFFu, m3, o));
        }
        float4 av = {0.f, 0.f, 0.f, 0.f};
        if (lane < d) {
            av.x = __expf(rv.x - m0);
            av.y = __expf(rv.y - m1);
            av.z = __expf(rv.z - m2);
            av.w = __expf(rv.w - m3);
        }
        float s0 = av.x, s1 = av.y, s2 = av.z, s3 = av.w;
#pragma unroll
        for (int o = 16; o; o >>= 1) {
            s0 += __shfl_xor_sync(0xFFFFFFFFu, s0, o);
            s1 += __shfl_xor_sync(0xFFFFFFFFu, s1, o);
            s2 += __shfl_xor_sync(0xFFFFFFFFu, s2, o);
            s3 += __shfl_xor_sync(0xFFFFFFFFu, s3, o);
        }
        av.x *= 1.f / (s0 + 1e-16f);
        av.y *= 1.f / (s1 + 1e-16f);
        av.z *= 1.f / (s2 + 1e-16f);
        av.w *= 1.f / (s3 + 1e-16f);
        if (lane < d) *(float4*)&alpha[e * 4] = av;

#pragma unroll 8
        for (int li = 0; li < d; li++) {
            int sb  = __shfl_sync(0xFFFFFFFFu, src, li);
            float w0 = __shfl_sync(0xFFFFFFFFu, av.x, li);
            float w1 = __shfl_sync(0xFFFFFFFFu, av.y, li);
            float w2 = __shfl_sync(0xFFFFFFFFu, av.z, li);
            float w3 = __shfl_sync(0xFFFFFFFFu, av.w, li);
            float2 xv = *(const float2*)&x[sb * F_IN + c0];
            a0.x += w0 * xv.x; a0.y += w0 * xv.y;
            a1.x += w1 * xv.x; a1.y += w1 * xv.y;
            a2.x += w2 * xv.x; a2.y += w2 * xv.y;
            a3.x += w3 * xv.x; a3.y += w3 * xv.y;
        }
    } else {
        // slow path (rare): chunked, register-only, 3 passes
        float m0 = -INFINITY, m1 = -INFINITY, m2 = -INFINITY, m3 = -INFINITY;
        for (int i = start + lane; i < end; i += 32) {
            int2 es = g_csr2[i];
            float4 as = *(const float4*)&g_asrc[es.y * HEADS];
            float v, r;
            v = as.x + ad.x; r = (v > 0.f) ? v : 0.2f * v; m0 = fmaxf(m0, r);
            v = as.y + ad.y; r = (v > 0.f) ? v : 0.2f * v; m1 = fmaxf(m1, r);
            v = as.z + ad.z; r = (v > 0.f) ? v : 0.2f * v; m2 = fmaxf(m2, r);
            v = as.w + ad.w; r = (v > 0.f) ? v : 0.2f * v; m3 = fmaxf(m3, r);
        }
#pragma unroll
        for (int o = 16; o; o >>= 1) {
            m0 = fmaxf(m0, __shfl_xor_sync(0xFFFFFFFFu, m0, o));
            m1 = fmaxf(m1, __shfl_xor_sync(0xFFFFFFFFu, m1, o));
            m2 = fmaxf(m2, __shfl_xor_sync(0xFFFFFFFFu, m2, o));
            m3 = fmaxf(m3, __shfl_xor_sync(0xFFFFFFFFu, m3, o));
        }
        float s0 = 0.f, s1 = 0.f, s2 = 0.f, s3 = 0.f;
        for (int i = start + lane; i < end; i += 32) {
            int2 es = g_csr2[i];
            float4 as = *(const float4*)&g_asrc[es.y * HEADS];
            float v, r; float4 ev;
            v = as.x + ad.x; r = (v > 0.f) ? v : 0.2f * v; ev.x = __expf(r - m0); s0 += ev.x;
            v = as.y + ad.y; r = (v > 0.f) ? v : 0.2f * v; ev.y = __expf(r - m1); s1 += ev.y;
            v = as.z + ad.z; r = (v > 0.f) ? v : 0.2f * v; ev.z = __expf(r - m2); s2 += ev.z;
            v = as.w + ad.w; r = (v > 0.f) ? v : 0.2f * v; ev.w = __expf(r - m3); s3 += ev.w;
            *(float4*)&alpha[es.x * 4] = ev;
        }
#pragma unroll
        for (int o = 16; o; o >>= 1) {
            s0 += __shfl_xor_sync(0xFFFFFFFFu, s0, o);
            s1 += __shfl_xor_sync(0xFFFFFFFFu, s1, o);
            s2 += __shfl_xor_sync(0xFFFFFFFFu, s2, o);
            s3 += __shfl_xor_sync(0xFFFFFFFFu, s3, o);
        }
        float i0 = 1.f / (s0 + 1e-16f), i1 = 1.f / (s1 + 1e-16f);
        float i2 = 1.f / (s2 + 1e-16f), i3 = 1.f / (s3 + 1e-16f);
        for (int base = start; base < end; base += 32) {
            int li = base + lane;
            int cl = min(32, end - base);
            int src = 0; float4 av = {0.f, 0.f, 0.f, 0.f};
            if (li < end) {
                int2 es = g_csr2[li];
                src = es.y;
                av = *(float4*)&alpha[es.x * 4];
                av.x *= i0; av.y *= i1; av.z *= i2; av.w *= i3;
                *(float4*)&alpha[es.x * 4] = av;
            }
            for (int k = 0; k < cl; k++) {
                int sb  = __shfl_sync(0xFFFFFFFFu, src, k);
                float w0 = __shfl_sync(0xFFFFFFFFu, av.x, k);
                float w1 = __shfl_sync(0xFFFFFFFFu, av.y, k);
                float w2 = __shfl_sync(0xFFFFFFFFu, av.z, k);
                float w3 = __shfl_sync(0xFFFFFFFFu, av.w, k);
                float2 xv = *(const float2*)&x[sb * F_IN + c0];
                a0.x += w0 * xv.x; a0.y += w0 * xv.y;
                a1.x += w1 * xv.x; a1.y += w1 * xv.y;
                a2.x += w2 * xv.x; a2.y += w2 * xv.y;
                a3.x += w3 * xv.x; a3.y += w3 * xv.y;
            }
        }
    }
    *(float2*)&g_s[n * HC + 0 * 64 + c0] = a0;
    *(float2*)&g_s[n * HC + 1 * 64 + c0] = a1;
    *(float2*)&g_s[n * HC + 2 * 64 + c0] = a2;
    *(float2*)&g_s[n * HC + 3 * 64 + c0] = a3;
}

// ---------------- post-transform + fused GraphNorm stats ----------------
#define PO_NPB 48
__global__ __launch_bounds__(256) void k_post_gn(const float* __restrict__ lin_w,
                                                 const float* __restrict__ gat_bias,
                                                 const int* __restrict__ batch) {
    __shared__ __align__(16) float ss[PO_NPB * HC];   // 48KB
    __shared__ int sb[PO_NPB];
    int j = threadIdx.x;
    float wreg[F_IN];
#pragma unroll
    for (int c = 0; c < F_IN; c++) wreg[c] = lin_w[j * F_IN + c];
    float bj = gat_bias[j];
    int hoff = (j >> 6) * 64;

    int n0 = blockIdx.x * PO_NPB;
    int nmax = min(PO_NPB, N_NODES - n0);
    {
        const float4* gs4 = (const float4*)&g_s[n0 * HC];
        float4* ss4 = (float4*)ss;
        int cnt4 = nmax * HC / 4;
        for (int t = j; t < cnt4; t += 256) ss4[t] = gs4[t];
    }
    if (j < nmax) sb[j] = batch[n0 + j];
    __syncthreads();

    float sum = 0.f, sq = 0.f;
    int curg = sb[0];
    for (int nn = 0; nn < nmax; nn++) {
        int g = sb[nn];
        if (g != curg) {
            atomicAdd(&g_mean[curg * HC + j], sum);
            atomicAdd(&g_var[curg * HC + j], sq);
            sum = 0.f; sq = 0.f; curg = g;
        }
        const float4* sp = (const float4*)&ss[nn * HC + hoff];
        float acc = 0.f;
#pragma unroll
        for (int c4 = 0; c4 < F_IN / 4; c4++) {
            float4 v = sp[c4];
            acc += v.x * wreg[4 * c4] + v.y * wreg[4 * c4 + 1]
                 + v.z * wreg[4 * c4 + 2] + v.w * wreg[4 * c4 + 3];
        }
        acc += bj;
        g_x2[(n0 + nn) * HC + j] = acc;
        sum += acc; sq += acc * acc;
    }
    atomicAdd(&g_mean[curg * HC + j], sum);
    atomicAdd(&g_var[curg * HC + j], sq);
}

// ---------------- fused norm-apply + ReLU + gate MLP + pool accumulate ----------------
#define AG_NPB 16
__global__ __launch_bounds__(256) void k_gatepool(const int* __restrict__ batch,
                                                  const float* __restrict__ mscale,
                                                  const float* __restrict__ gw,
                                                  const float* __restrict__ gb,
                                                  const float* __restrict__ att1_w,
                                                  const float* __restrict__ att1_b,
                                                  const float* __restrict__ att2_w,
                                                  const float* __restrict__ att2_b) {
    __shared__ float wsT[HC * 16];                      // [c][k]
    __shared__ __align__(16) float hs[AG_NPB * HC];
    __shared__ float eg[AG_NPB];
    __shared__ int sb[AG_NPB];
    int j = threadIdx.x;
    for (int t = j; t < 16 * HC; t += 256) {
        int k = t >> 8, c = t & 255;
        wsT[c * 16 + k] = att1_w[t];
    }
    int n0 = blockIdx.x * AG_NPB;
    if (j < AG_NPB) sb[j] = batch[n0 + j];
    float msj = mscale[j], wj = gw[j], bj = gb[j];
    __syncthreads();

    int lastg = -1;
    float cA = 0.f, cB = 0.f;
    for (int nn = 0; nn < AG_NPB; nn++) {
        int g = sb[nn];
        if (g != lastg) {
            float cnt = fmaxf((float)(g_ge[g] - g_gs[g]), 1.f);
            float inv = 1.f / cnt;
            float mean = g_mean[g * HC + j] * inv;
            float ex2 = g_var[g * HC + j] * inv;
            float mm = mean * msj;
            float var = ex2 - 2.f * mm * mean + mm * mm;
            cA = wj * rsqrtf(var + 1e-5f);
            cB = bj - cA * mm;
            lastg = g;
        }
        float h = fmaxf(cA * g_x2[(n0 + nn) * HC + j] + cB, 0.f);
        hs[nn * HC + j] = h;
    }
    __syncthreads();

    {
        int nn = j >> 4, k = j & 15;
        float acc = att1_b[k];
        const float4* hp = (const float4*)&hs[nn * HC];
#pragma unroll 8
        for (int c4 = 0; c4 < HC / 4; c4++) {
            float4 v = hp[c4];
            int c = c4 * 4;
            acc += v.x * wsT[c * 16 + k] + v.y * wsT[(c + 1) * 16 + k]
                 + v.z * wsT[(c + 2) * 16 + k] + v.w * wsT[(c + 3) * 16 + k];
        }
        float r = fmaxf(acc, 0.f) * att2_w[k];
#pragma unroll
        for (int o = 8; o; o >>= 1) r += __shfl_xor_sync(0xFFFFFFFFu, r, o);
        if (k == 0) {
            float gate = 1.f / (1.f + __expf(-(r + att2_b[0])));
            eg[nn] = __expf(gate);
        }
    }
    __syncthreads();

    float pacc = 0.f;
    int curg = sb[0];
    for (int nn = 0; nn < AG_NPB; nn++) {
        int g = sb[nn];
        if (g != curg) {
            atomicAdd(&g_pool[curg * HC + j], pacc);
            pacc = 0.f; curg = g;
        }
        pacc += eg[nn] * hs[nn * HC + j];
    }
    atomicAdd(&g_pool[curg * HC + j], pacc);
    if (j < AG_NPB) atomicAdd(&g_gden[sb[j]], eg[j]);
}

// ---------------- head ----------------
__global__ void k_head(const float* __restrict__ fc1_w, const float* __restrict__ fc1_b,
                       const float* __restrict__ out_w, const float* __restrict__ out_b,
                       float* __restrict__ out) {
    int g = blockIdx.x, o = threadIdx.x;  // 128 threads
    float invZ = 1.f / (g_gden[g] + 1e-16f);
    float acc = fc1_b[o];
    const float* p = &g_pool[g * HC];
    const float* w = &fc1_w[o * HC];
#pragma unroll 8
    for (int c = 0; c < HC; c++) acc += p[c] * invZ * w[c];
    acc = fmaxf(acc, 0.f) * out_w[o];
    __shared__ float red[ODIM];
    red[o] = acc;
    __syncthreads();
#pragma unroll
    for (int s = 64; s; s >>= 1) {
        if (o < s) red[o] += red[o + s];
        __syncthreads();
    }
    if (o == 0) out[g] = 1.f / (1.f + __expf(-(red[0] + out_b[0])));
}

// ---------------- launch ----------------
extern "C" void kernel_launch(void* const* d_in, const int* in_sizes, int n_in,
                              void* d_out, int out_size) {
    const float* x        = (const float*)d_in[0];
    const int*   ei       = (const int*)  d_in[1];
    const int*   batch    = (const int*)  d_in[2];
    const float* lin_w    = (const float*)d_in[3];
    const float* att_src  = (const float*)d_in[4];
    const float* att_dst  = (const float*)d_in[5];
    const float* gat_bias = (const float*)d_in[6];
    const float* gn_w     = (const float*)d_in[7];
    const float* gn_b     = (const float*)d_in[8];
    const float* gn_ms    = (const float*)d_in[9];
    const float* fc1_w    = (const float*)d_in[10];
    const float* fc1_b    = (const float*)d_in[11];
    const float* out_w    = (const float*)d_in[12];
    const float* out_b    = (const float*)d_in[13];
    const float* att1_w   = (const float*)d_in[14];
    const float* att1_b   = (const float*)d_in[15];
    const float* att2_w   = (const float*)d_in[16];
    const float* att2_b   = (const float*)d_in[17];

    float* out   = (float*)d_out;
    float* alpha = out + NGRAPH;   // [NTOT, HEADS]

    k_prew<<<1, 256>>>(lin_w, att_src, att_dst);
    k_front<<<SC_BLKS + HI_BLKS + BD_BLKS, 256>>>(x, ei, batch);
    k_scan<<<NBLK_SCAN, 256>>>();
    k_fill<<<FI_BLKS + ZR_BLKS, 256>>>(ei);
    k_gat<<<(N_NODES + GAT_WARPS - 1) / GAT_WARPS, 256>>>(x, alpha);
    k_post_gn<<<(N_NODES + PO_NPB - 1) / PO_NPB, 256>>>(lin_w, gat_bias, batch);
    k_gatepool<<<N_NODES / AG_NPB, 256>>>(batch, gn_ms, gn_w, gn_b,
                                          att1_w, att1_b, att2_w, att2_b);
    k_head<<<NGRAPH, ODIM>>>(fc1_w, fc1_b, out_w, out_b, out);
}

// round 17
// speedup vs baseline: 1.8912x; 1.0122x over previous
#include <cuda_runtime.h>
#include <math.h>

#define N_NODES 50000
#define N_EDGES 800000
#define NTOT    850000   // E + N self loops
#define NGRAPH  256
#define F_IN    64
#define HEADS   4
#define HC      256      // HEADS*F_IN
#define ODIM    128
#define NBLK_SCAN 196    // ceil(N_NODES/256)

// ---------------- scratch (device globals; no allocation) ----------------
__device__ __align__(16) float g_s   [N_NODES * HC];
__device__ __align__(16) float g_asrc[N_NODES * HEADS];
__device__ __align__(16) float g_adst[N_NODES * HEADS];
__device__ __align__(16) float g_x2  [N_NODES * HC];
__device__ __align__(16) float g_pool[NGRAPH * HC];
__device__ float g_gden[NGRAPH];
__device__ __align__(16) float g_mean[NGRAPH * HC];
__device__ __align__(16) float g_var [NGRAPH * HC];
__device__ __align__(16) float g_wsrc[HC];
__device__ __align__(16) float g_wdst[HC];
__device__ __align__(16) int   g_deg [N_NODES];
__device__ int   g_rowptr[N_NODES + 1];
__device__ int   g_woff[N_NODES];
__device__ __align__(16) int2  g_csr2[NTOT];
__device__ int   g_gs  [NGRAPH];
__device__ int   g_ge  [NGRAPH];

// ---------------- side stream + events (created at static init, pre-checkpoint) ----------------
static cudaStream_t g_s2;
static cudaEvent_t  g_evFork, g_evJoin;
struct _StreamInit {
    _StreamInit() {
        cudaStreamCreateWithFlags(&g_s2, cudaStreamNonBlocking);
        cudaEventCreateWithFlags(&g_evFork, cudaEventDisableTiming);
        cudaEventCreateWithFlags(&g_evJoin, cudaEventDisableTiming);
    }
};
static _StreamInit g_si;

// ---------------- prew: projected attention vectors (1 block) ----------------
__global__ void k_prew(const float* __restrict__ lin_w,
                       const float* __restrict__ att_src,
                       const float* __restrict__ att_dst) {
    int t = threadIdx.x;          // t = h*64 + c
    int h = t >> 6, c = t & 63;
    float as = 0.f, ad = 0.f;
    for (int j = 0; j < F_IN; j++) {
        float w = lin_w[(h * F_IN + j) * F_IN + c];
        as += att_src[h * F_IN + j] * w;
        ad += att_dst[h * F_IN + j] * w;
    }
    g_wsrc[t] = as;
    g_wdst[t] = ad;
}

// ---------------- scores: warp per node ----------------
#define SC_BLKS 6250
__global__ __launch_bounds__(256) void k_scores(const float* __restrict__ x) {
    int warp = threadIdx.x >> 5, lane = threadIdx.x & 31;
    int n = blockIdx.x * 8 + warp;
    if (n >= N_NODES) return;
    float2 xv = *(const float2*)&x[n * F_IN + lane * 2];
    float p0, p1, p2, p3, q0, q1, q2, q3;
    {
        float2 w;
        w = *(const float2*)&g_wsrc[0 * 64 + lane * 2]; p0 = w.x * xv.x + w.y * xv.y;
        w = *(const float2*)&g_wsrc[1 * 64 + lane * 2]; p1 = w.x * xv.x + w.y * xv.y;
        w = *(const float2*)&g_wsrc[2 * 64 + lane * 2]; p2 = w.x * xv.x + w.y * xv.y;
        w = *(const float2*)&g_wsrc[3 * 64 + lane * 2]; p3 = w.x * xv.x + w.y * xv.y;
        w = *(const float2*)&g_wdst[0 * 64 + lane * 2]; q0 = w.x * xv.x + w.y * xv.y;
        w = *(const float2*)&g_wdst[1 * 64 + lane * 2]; q1 = w.x * xv.x + w.y * xv.y;
        w = *(const float2*)&g_wdst[2 * 64 + lane * 2]; q2 = w.x * xv.x + w.y * xv.y;
        w = *(const float2*)&g_wdst[3 * 64 + lane * 2]; q3 = w.x * xv.x + w.y * xv.y;
    }
#pragma unroll
    for (int o = 16; o; o >>= 1) {
        p0 += __shfl_xor_sync(0xFFFFFFFFu, p0, o);
        p1 += __shfl_xor_sync(0xFFFFFFFFu, p1, o);
        p2 += __shfl_xor_sync(0xFFFFFFFFu, p2, o);
        p3 += __shfl_xor_sync(0xFFFFFFFFu, p3, o);
        q0 += __shfl_xor_sync(0xFFFFFFFFu, q0, o);
        q1 += __shfl_xor_sync(0xFFFFFFFFu, q1, o);
        q2 += __shfl_xor_sync(0xFFFFFFFFu, q2, o);
        q3 += __shfl_xor_sync(0xFFFFFFFFu, q3, o);
    }
    if (lane == 0) {
        float4 a = {p0, p1, p2, p3};
        float4 bb = {q0, q1, q2, q3};
        *(float4*)&g_asrc[n * HEADS] = a;
        *(float4*)&g_adst[n * HEADS] = bb;
    }
}

// ---------------- hist + bounds ----------------
#define HI_BLKS 3321
#define BD_BLKS 196
__global__ __launch_bounds__(256) void k_histbounds(const int* __restrict__ ei,
                                                    const int* __restrict__ batch) {
    int b = blockIdx.x;
    if (b < HI_BLKS) {
        int e = b * 256 + threadIdx.x;
        if (e >= NTOT) return;
        int dst = (e < N_EDGES) ? ei[N_EDGES + e] : (e - N_EDGES);
        atomicAdd(&g_deg[dst], 1);
    } else {
        int n = (b - HI_BLKS) * 256 + threadIdx.x;
        if (n >= N_NODES) return;
        int g = batch[n];
        if (n == 0 || batch[n - 1] != g) g_gs[g] = n;
        if (n == N_NODES - 1 || batch[n + 1] != g) g_ge[g] = n + 1;
    }
}

// ---------------- CSR scan: single kernel; each block computes its own prefix ----------------
__global__ __launch_bounds__(256) void k_scan() {
    __shared__ int sm[256];
    __shared__ int wsum[8];
    int b = blockIdx.x, t = threadIdx.x;
    int lane = t & 31, warp = t >> 5;

    int pre = 0;
    const int4* d4 = (const int4*)g_deg;
    int n4 = b * 64;
    for (int i = t; i < n4; i += 256) {
        int4 v = d4[i];
        pre += v.x + v.y + v.z + v.w;
    }
#pragma unroll
    for (int o = 16; o; o >>= 1) pre += __shfl_xor_sync(0xFFFFFFFFu, pre, o);
    if (lane == 0) wsum[warp] = pre;

    int idx = b * 256 + t;
    int v = (idx < N_NODES) ? g_deg[idx] : 0;
    sm[t] = v;
    __syncthreads();
#pragma unroll
    for (int o = 1; o < 256; o <<= 1) {
        int u = (t >= o) ? sm[t - o] : 0;
        __syncthreads();
        sm[t] += u;
        __syncthreads();
    }
    int tot = wsum[0] + wsum[1] + wsum[2] + wsum[3]
            + wsum[4] + wsum[5] + wsum[6] + wsum[7];
    if (idx < N_NODES) {
        int r = tot + sm[t] - v;
        g_rowptr[idx] = r;
        g_woff[idx] = r;
    }
    if (b == 0 && t == 0) g_rowptr[N_NODES] = NTOT;
}

// ---------------- fill CSR (+ self-clean zeroing in extra blocks) ----------------
#define FI_BLKS 3321
#define ZR_BLKS 257
__global__ void k_fill(const int* __restrict__ ei) {
    int b = blockIdx.x;
    if (b >= FI_BLKS) {
        int i = (b - FI_BLKS) * 256 + threadIdx.x;
        if (i < N_NODES) g_deg[i] = 0;
        if (i < NGRAPH * HC) { g_mean[i] = 0.f; g_var[i] = 0.f; g_pool[i] = 0.f; }
        if (i < NGRAPH) g_gden[i] = 0.f;
        return;
    }
    int e = b * 256 + threadIdx.x;
    if (e >= NTOT) return;
    int src, dst;
    if (e < N_EDGES) { src = ei[e]; dst = ei[N_EDGES + e]; }
    else             { src = dst = e - N_EDGES; }
    int pos = atomicAdd(&g_woff[dst], 1);
    int2 es; es.x = e; es.y = src;
    g_csr2[pos] = es;
}

// ---------------- fused GAT: warp per dst node, register-resident ----------------
#define GAT_WARPS 8
__global__ __launch_bounds__(256) void k_gat(const float* __restrict__ x,
                                             float* __restrict__ alpha) {
    int warp = threadIdx.x >> 5;
    int lane = threadIdx.x & 31;
    int n = blockIdx.x * GAT_WARPS + warp;
    if (n >= N_NODES) return;
    int start = g_rowptr[n], end = g_rowptr[n + 1];
    int d = end - start;
    float4 ad = *(const float4*)&g_adst[n * HEADS];
    int c0 = lane * 2;

    float2 a0 = {0.f,0.f}, a1 = {0.f,0.f}, a2 = {0.f,0.f}, a3 = {0.f,0.f};

    if (d <= 32) {
        int e = 0, src = 0;
        float4 rv = {-INFINITY, -INFINITY, -INFINITY, -INFINITY};
        if (lane < d) {
            int2 es = g_csr2[start + lane];
            e = es.x; src = es.y;
            float4 as = *(const float4*)&g_asrc[src * HEADS];
            float v;
            v = as.x + ad.x; rv.x = (v > 0.f) ? v : 0.2f * v;
            v = as.y + ad.y; rv.y = (v > 0.f) ? v : 0.2f * v;
            v = as.z + ad.z; rv.z = (v > 0.f) ? v : 0.2f * v;
            v = as.w + ad.w; rv.w = (v > 0.f) ? v : 0.2f * v;
        }
        float m0 = rv.x, m1 = rv.y, m2 = rv.z, m3 = rv.w;
#pragma unroll
        for (int o = 16; o; o >>= 1) {
            m0 = fmaxf(m0, __shfl_xor_sync(0xFFFFFFFFu, m0, o));
            m1 = fmaxf(m1, __shfl_xor_sync(0xFFFFFFFFu, m1, o));
            m2 = fmaxf(m2, __shfl_xor_sync(0xFFFFFFFFu, m2, o));
            m3 = fmaxf(m3, __shfl_xor_sync(0xFFFFFFFFu, m3, o));
        }
        float4 av = {0.f, 0.f, 0.f, 0.f};
        if (lane < d) {
            av.x = __expf(rv.x - m0);
            av.y = __expf(rv.y - m1);
            av.z = __expf(rv.z - m2);
            av.w = __expf(rv.w - m3);
        }
        float s0 = av.x, s1 = av.y, s2 = av.z, s3 = av.w;
#pragma unroll
        for (int o = 16; o; o >>= 1) {
            s0 += __shfl_xor_sync(0xFFFFFFFFu, s0, o);
            s1 += __shfl_xor_sync(0xFFFFFFFFu, s1, o);
            s2 += __shfl_xor_sync(0xFFFFFFFFu, s2, o);
            s3 += __shfl_xor_sync(0xFFFFFFFFu, s3, o);
        }
        av.x *= 1.f / (s0 + 1e-16f);
        av.y *= 1.f / (s1 + 1e-16f);
        av.z *= 1.f / (s2 + 1e-16f);
        av.w *= 1.f / (s3 + 1e-16f);
        if (lane < d) *(float4*)&alpha[e * 4] = av;

#pragma unroll 8
        for (int li = 0; li < d; li++) {
            int sb  = __shfl_sync(0xFFFFFFFFu, src, li);
            float w0 = __shfl_sync(0xFFFFFFFFu, av.x, li);
            float w1 = __shfl_sync(0xFFFFFFFFu, av.y, li);
            float w2 = __shfl_sync(0xFFFFFFFFu, av.z, li);
            float w3 = __shfl_sync(0xFFFFFFFFu, av.w, li);
            float2 xv = *(const float2*)&x[sb * F_IN + c0];
            a0.x += w0 * xv.x; a0.y += w0 * xv.y;
            a1.x += w1 * xv.x; a1.y += w1 * xv.y;
            a2.x += w2 * xv.x; a2.y += w2 * xv.y;
            a3.x += w3 * xv.x; a3.y += w3 * xv.y;
        }
    } else {
        // slow path (rare): chunked, register-only, 3 passes
        float m0 = -INFINITY, m1 = -INFINITY, m2 = -INFINITY, m3 = -INFINITY;
        for (int i = start + lane; i < end; i += 32) {
            int2 es = g_csr2[i];
            float4 as = *(const float4*)&g_asrc[es.y * HEADS];
            float v, r;
            v = as.x + ad.x; r = (v > 0.f) ? v : 0.2f * v; m0 = fmaxf(m0, r);
            v = as.y + ad.y; r = (v > 0.f) ? v : 0.2f * v; m1 = fmaxf(m1, r);
            v = as.z + ad.z; r = (v > 0.f) ? v : 0.2f * v; m2 = fmaxf(m2, r);
            v = as.w + ad.w; r = (v > 0.f) ? v : 0.2f * v; m3 = fmaxf(m3, r);
        }
#pragma unroll
        for (int o = 16; o; o >>= 1) {
            m0 = fmaxf(m0, __shfl_xor_sync(0xFFFFFFFFu, m0, o));
            m1 = fmaxf(m1, __shfl_xor_sync(0xFFFFFFFFu, m1, o));
            m2 = fmaxf(m2, __shfl_xor_sync(0xFFFFFFFFu, m2, o));
            m3 = fmaxf(m3, __shfl_xor_sync(0xFFFFFFFFu, m3, o));
        }
        float s0 = 0.f, s1 = 0.f, s2 = 0.f, s3 = 0.f;
        for (int i = start + lane; i < end; i += 32) {
            int2 es = g_csr2[i];
            float4 as = *(const float4*)&g_asrc[es.y * HEADS];
            float v, r; float4 ev;
            v = as.x + ad.x; r = (v > 0.f) ? v : 0.2f * v; ev.x = __expf(r - m0); s0 += ev.x;
            v = as.y + ad.y; r = (v > 0.f) ? v : 0.2f * v; ev.y = __expf(r - m1); s1 += ev.y;
            v = as.z + ad.z; r = (v > 0.f) ? v : 0.2f * v; ev.z = __expf(r - m2); s2 += ev.z;
            v = as.w + ad.w; r = (v > 0.f) ? v : 0.2f * v; ev.w = __expf(r - m3); s3 += ev.w;
            *(float4*)&alpha[es.x * 4] = ev;
        }
#pragma unroll
        for (int o = 16; o; o >>= 1) {
            s0 += __shfl_xor_sync(0xFFFFFFFFu, s0, o);
            s1 += __shfl_xor_sync(0xFFFFFFFFu, s1, o);
            s2 += __shfl_xor_sync(0xFFFFFFFFu, s2, o);
            s3 += __shfl_xor_sync(0xFFFFFFFFu, s3, o);
        }
        float i0 = 1.f / (s0 + 1e-16f), i1 = 1.f / (s1 + 1e-16f);
        float i2 = 1.f / (s2 + 1e-16f), i3 = 1.f / (s3 + 1e-16f);
        for (int base = start; base < end; base += 32) {
            int li = base + lane;
            int cl = min(32, end - base);
            int src = 0; float4 av = {0.f, 0.f, 0.f, 0.f};
            if (li < end) {
                int2 es = g_csr2[li];
                src = es.y;
                av = *(float4*)&alpha[es.x * 4];
                av.x *= i0; av.y *= i1; av.z *= i2; av.w *= i3;
                *(float4*)&alpha[es.x * 4] = av;
            }
            for (int k = 0; k < cl; k++) {
                int sb  = __shfl_sync(0xFFFFFFFFu, src, k);
                float w0 = __shfl_sync(0xFFFFFFFFu, av.x, k);
                float w1 = __shfl_sync(0xFFFFFFFFu, av.y, k);
                float w2 = __shfl_sync(0xFFFFFFFFu, av.z, k);
                float w3 = __shfl_sync(0xFFFFFFFFu, av.w, k);
                float2 xv = *(const float2*)&x[sb * F_IN + c0];
                a0.x += w0 * xv.x; a0.y += w0 * xv.y;
                a1.x += w1 * xv.x; a1.y += w1 * xv.y;
                a2.x += w2 * xv.x; a2.y += w2 * xv.y;
                a3.x += w3 * xv.x; a3.y += w3 * xv.y;
            }
        }
    }
    *(float2*)&g_s[n * HC + 0 * 64 + c0] = a0;
    *(float2*)&g_s[n * HC + 1 * 64 + c0] = a1;
    *(float2*)&g_s[n * HC + 2 * 64 + c0] = a2;
    *(float2*)&g_s[n * HC + 3 * 64 + c0] = a3;
}

// ---------------- post-transform + fused GraphNorm stats ----------------
#define PO_NPB 48
__global__ __launch_bounds__(256) void k_post_gn(const float* __restrict__ lin_w,
                                                 const float* __restrict__ gat_bias,
                                                 const int* __restrict__ batch) {
    __shared__ __align__(16) float ss[PO_NPB * HC];   // 48KB
    __shared__ int sb[PO_NPB];
    int j = threadIdx.x;
    float wreg[F_IN];
#pragma unroll
    for (int c = 0; c < F_IN; c++) wreg[c] = lin_w[j * F_IN + c];
    float bj = gat_bias[j];
    int hoff = (j >> 6) * 64;

    int n0 = blockIdx.x * PO_NPB;
    int nmax = min(PO_NPB, N_NODES - n0);
    {
        const float4* gs4 = (const float4*)&g_s[n0 * HC];
        float4* ss4 = (float4*)ss;
        int cnt4 = nmax * HC / 4;
        for (int t = j; t < cnt4; t += 256) ss4[t] = gs4[t];
    }
    if (j < nmax) sb[j] = batch[n0 + j];
    __syncthreads();

    float sum = 0.f, sq = 0.f;
    int curg = sb[0];
    for (int nn = 0; nn < nmax; nn++) {
        int g = sb[nn];
        if (g != curg) {
            atomicAdd(&g_mean[curg * HC + j], sum);
            atomicAdd(&g_var[curg * HC + j], sq);
            sum = 0.f; sq = 0.f; curg = g;
        }
        const float4* sp = (const float4*)&ss[nn * HC + hoff];
        float acc = 0.f;
#pragma unroll
        for (int c4 = 0; c4 < F_IN / 4; c4++) {
            float4 v = sp[c4];
            acc += v.x * wreg[4 * c4] + v.y * wreg[4 * c4 + 1]
                 + v.z * wreg[4 * c4 + 2] + v.w * wreg[4 * c4 + 3];
        }
        acc += bj;
        g_x2[(n0 + nn) * HC + j] = acc;
        sum += acc; sq += acc * acc;
    }
    atomicAdd(&g_mean[curg * HC + j], sum);
    atomicAdd(&g_var[curg * HC + j], sq);
}

// ---------------- fused norm-apply + ReLU + gate MLP + pool accumulate ----------------
#define AG_NPB 16
__global__ __launch_bounds__(256) void k_gatepool(const int* __restrict__ batch,
                                                  const float* __restrict__ mscale,
                                                  const float* __restrict__ gw,
                                                  const float* __restrict__ gb,
                                                  const float* __restrict__ att1_w,
                                                  const float* __restrict__ att1_b,
                                                  const float* __restrict__ att2_w,
                                                  const float* __restrict__ att2_b) {
    __shared__ float wsT[HC * 16];                      // [c][k]
    __shared__ __align__(16) float hs[AG_NPB * HC];
    __shared__ float eg[AG_NPB];
    __shared__ int sb[AG_NPB];
    int j = threadIdx.x;
    for (int t = j; t < 16 * HC; t += 256) {
        int k = t >> 8, c = t & 255;
        wsT[c * 16 + k] = att1_w[t];
    }
    int n0 = blockIdx.x * AG_NPB;
    if (j < AG_NPB) sb[j] = batch[n0 + j];
    float msj = mscale[j], wj = gw[j], bj = gb[j];
    __syncthreads();

    int lastg = -1;
    float cA = 0.f, cB = 0.f;
    for (int nn = 0; nn < AG_NPB; nn++) {
        int g = sb[nn];
        if (g != lastg) {
            float cnt = fmaxf((float)(g_ge[g] - g_gs[g]), 1.f);
            float inv = 1.f / cnt;
            float mean = g_mean[g * HC + j] * inv;
            float ex2 = g_var[g * HC + j] * inv;
            float mm = mean * msj;
            float var = ex2 - 2.f * mm * mean + mm * mm;
            cA = wj * rsqrtf(var + 1e-5f);
            cB = bj - cA * mm;
            lastg = g;
        }
        float h = fmaxf(cA * g_x2[(n0 + nn) * HC + j] + cB, 0.f);
        hs[nn * HC + j] = h;
    }
    __syncthreads();

    {
        int nn = j >> 4, k = j & 15;
        float acc = att1_b[k];
        const float4* hp = (const float4*)&hs[nn * HC];
#pragma unroll 8
        for (int c4 = 0; c4 < HC / 4; c4++) {
            float4 v = hp[c4];
            int c = c4 * 4;
            acc += v.x * wsT[c * 16 + k] + v.y * wsT[(c + 1) * 16 + k]
                 + v.z * wsT[(c + 2) * 16 + k] + v.w * wsT[(c + 3) * 16 + k];
        }
        float r = fmaxf(acc, 0.f) * att2_w[k];
#pragma unroll
        for (int o = 8; o; o >>= 1) r += __shfl_xor_sync(0xFFFFFFFFu, r, o);
        if (k == 0) {
            float gate = 1.f / (1.f + __expf(-(r + att2_b[0])));
            eg[nn] = __expf(gate);
        }
    }
    __syncthreads();

    float pacc = 0.f;
    int curg = sb[0];
    for (int nn = 0; nn < AG_NPB; nn++) {
        int g = sb[nn];
        if (g != curg) {
            atomicAdd(&g_pool[curg * HC + j], pacc);
            pacc = 0.f; curg = g;
        }
        pacc += eg[nn] * hs[nn * HC + j];
    }
    atomicAdd(&g_pool[curg * HC + j], pacc);
    if (j < AG_NPB) atomicAdd(&g_gden[sb[j]], eg[j]);
}

// ---------------- head ----------------
__global__ void k_head(const float* __restrict__ fc1_w, const float* __restrict__ fc1_b,
                       const float* __restrict__ out_w, const float* __restrict__ out_b,
                       float* __restrict__ out) {
    int g = blockIdx.x, o = threadIdx.x;  // 128 threads
    float invZ = 1.f / (g_gden[g] + 1e-16f);
    float acc = fc1_b[o];
    const float* p = &g_pool[g * HC];
    const float* w = &fc1_w[o * HC];
#pragma unroll 8
    for (int c = 0; c < HC; c++) acc += p[c] * invZ * w[c];
    acc = fmaxf(acc, 0.f) * out_w[o];
    __shared__ float red[ODIM];
    red[o] = acc;
    __syncthreads();
#pragma unroll
    for (int s = 64; s; s >>= 1) {
        if (o < s) red[o] += red[o + s];
        __syncthreads();
    }
    if (o == 0) out[g] = 1.f / (1.f + __expf(-(red[0] + out_b[0])));
}

// ---------------- launch ----------------
extern "C" void kernel_launch(void* const* d_in, const int* in_sizes, int n_in,
                              void* d_out, int out_size) {
    const float* x        = (const float*)d_in[0];
    const int*   ei       = (const int*)  d_in[1];
    const int*   batch    = (const int*)  d_in[2];
    const float* lin_w    = (const float*)d_in[3];
    const float* att_src  = (const float*)d_in[4];
    const float* att_dst  = (const float*)d_in[5];
    const float* gat_bias = (const float*)d_in[6];
    const float* gn_w     = (const float*)d_in[7];
    const float* gn_b     = (const float*)d_in[8];
    const float* gn_ms    = (const float*)d_in[9];
    const float* fc1_w    = (const float*)d_in[10];
    const float* fc1_b    = (const float*)d_in[11];
    const float* out_w    = (const float*)d_in[12];
    const float* out_b    = (const float*)d_in[13];
    const float* att1_w   = (const float*)d_in[14];
    const float* att1_b   = (const float*)d_in[15];
    const float* att2_w   = (const float*)d_in[16];
    const float* att2_b   = (const float*)d_in[17];

    float* out   = (float*)d_out;
    float* alpha = out + NGRAPH;   // [NTOT, HEADS]

    // Fork: side stream runs prew+scores while main stream builds the CSR.
    cudaEventRecord(g_evFork, 0);
    cudaStreamWaitEvent(g_s2, g_evFork, 0);
    k_prew<<<1, 256, 0, g_s2>>>(lin_w, att_src, att_dst);
    k_scores<<<SC_BLKS, 256, 0, g_s2>>>(x);
    cudaEventRecord(g_evJoin, g_s2);

    k_histbounds<<<HI_BLKS + BD_BLKS, 256>>>(ei, batch);
    k_scan<<<NBLK_SCAN, 256>>>();
    k_fill<<<FI_BLKS + ZR_BLKS, 256>>>(ei);

    // Join before GAT (needs both asrc/adst and the CSR).
    cudaStreamWaitEvent(0, g_evJoin, 0);
    k_gat<<<(N_NODES + GAT_WARPS - 1) / GAT_WARPS, 256>>>(x, alpha);
    k_post_gn<<<(N_NODES + PO_NPB - 1) / PO_NPB, 256>>>(lin_w, gat_bias, batch);
    k_gatepool<<<N_NODES / AG_NPB, 256>>>(batch, gn_ms, gn_w, gn_b,
                                          att1_w, att1_b, att2_w, att2_b);
    k_head<<<NGRAPH, ODIM>>>(fc1_w, fc1_b, out_w, out_b, out);
}